// round 1
// baseline (speedup 1.0000x reference)
#include <cuda_runtime.h>
#include <cuda_bf16.h>

#define NB      16384
#define HDIM    64
#define EMB     16
#define SEQ     30
#define NMODE   3
#define TB      16          // elements per block tile
#define THREADS 256
#define WSTRIDE 84          // padded weight row (80 used) -> conflict-free LDS.128
#define HSTRIDE 68          // padded h/c row (64 used)
#define NTILES  (NB * NMODE / TB)   // 3072

// SMEM layout (floats)
#define OFF_SW   0
#define OFF_SB   (OFF_SW  + 256 * WSTRIDE)   // 21504
#define OFF_SH   (OFF_SB  + 256)             // 21760
#define OFF_SC   (OFF_SH  + TB * HSTRIDE)    // 22848
#define OFF_SX   (OFF_SC  + TB * HSTRIDE)    // 23936
#define OFF_SWP  (OFF_SX  + TB * EMB)        // 24192
#define OFF_SWE  (OFF_SWP + 2 * HDIM)        // 24320
#define OFF_SBE  (OFF_SWE + EMB * 2)         // 24352
#define OFF_SBP  (OFF_SBE + EMB)             // 24368
#define SMEM_FLOATS (OFF_SBP + 2)            // 24370
#define SMEM_BYTES  (SMEM_FLOATS * 4)        // 97480

__device__ float g_hfin[NMODE * NB * HDIM];  // final hidden states scratch (12.6 MB, static)

__device__ __forceinline__ float sigmoidf_(float x) {
    return __fdividef(1.0f, 1.0f + __expf(-x));
}
__device__ __forceinline__ float tanh_fast(float x) {
    // tanh(x) = 2*sigmoid(2x) - 1 ; accurate to ~1e-6 rel, saturates correctly
    return __fdividef(2.0f, 1.0f + __expf(-2.0f * x)) - 1.0f;
}
__device__ __forceinline__ float lrelu_(float x) {
    return x > 0.0f ? x : 0.01f * x;
}

__global__ void __launch_bounds__(THREADS, 2)
lstm_main(const float* __restrict__ traj_rel,
          const float* __restrict__ h0,
          const float* __restrict__ c0,
          const float* __restrict__ W_ih,
          const float* __restrict__ W_hh,
          const float* __restrict__ b_ih,
          const float* __restrict__ b_hh,
          const float* __restrict__ We,
          const float* __restrict__ be,
          const float* __restrict__ Wp,
          const float* __restrict__ bp,
          float* __restrict__ out)
{
    extern __shared__ float smem[];
    float* sW  = smem + OFF_SW;    // [256][WSTRIDE] rows: gate g, cols 0..15 = W_ih, 16..79 = W_hh
    float* sb  = smem + OFF_SB;    // [256] combined bias
    float* sh  = smem + OFF_SH;    // [TB][HSTRIDE]
    float* sc  = smem + OFF_SC;    // [TB][HSTRIDE]
    float* sx  = smem + OFF_SX;    // [TB][EMB]
    float* sWp = smem + OFF_SWP;   // [2][64]  (this tile's mode)
    float* sWe = smem + OFF_SWE;   // [16][2]
    float* sbe = smem + OFF_SBE;   // [16]
    float* sbp = smem + OFF_SBP;   // [2]

    const int tid  = threadIdx.x;
    const int tile = blockIdx.x;          // 0..3071
    const int m    = tile >> 10;          // mode (1024 tiles per mode)
    const int e0   = (tile & 1023) * TB;  // first element of tile

    // ---- cooperative loads ----
    for (int idx = tid; idx < 256 * 80; idx += THREADS) {
        int g = idx / 80;
        int k = idx - g * 80;
        sW[g * WSTRIDE + k] = (k < EMB) ? W_ih[g * EMB + k]
                                        : W_hh[g * HDIM + (k - EMB)];
    }
    sb[tid] = b_ih[tid] + b_hh[tid];
    if (tid < 2 * HDIM) sWp[tid] = Wp[m * 2 * HDIM + tid];
    if (tid < EMB * 2)  sWe[tid] = We[tid];
    if (tid < EMB)      sbe[tid] = be[tid];
    if (tid < 2)        sbp[tid] = bp[m * 2 + tid];
    for (int idx = tid; idx < TB * HDIM; idx += THREADS) {
        int e = idx >> 6, k = idx & 63;
        sh[e * HSTRIDE + k] = h0[e0 * HDIM + idx];
        sc[e * HSTRIDE + k] = c0[e0 * HDIM + idx];
    }
    {   // x0 = leaky_relu(traj_rel @ We^T + be) : 16 elems x 16 dims = 256 threads
        int e = tid >> 4, k = tid & 15;
        float t0 = traj_rel[(e0 + e) * 2 + 0];
        float t1 = traj_rel[(e0 + e) * 2 + 1];
        sx[e * EMB + k] = lrelu_(t0 * We[k * 2 + 0] + t1 * We[k * 2 + 1] + be[k]);
    }
    __syncthreads();

    const int j  = tid & 63;   // hidden unit
    const int eg = tid >> 6;   // element group (4 elems each)
    const float4* w0p = (const float4*)(sW + (      j) * WSTRIDE);  // i
    const float4* w1p = (const float4*)(sW + ( 64 + j) * WSTRIDE);  // f
    const float4* w2p = (const float4*)(sW + (128 + j) * WSTRIDE);  // g
    const float4* w3p = (const float4*)(sW + (192 + j) * WSTRIDE);  // o
    const float biv = sb[j], bfv = sb[64 + j], bgv = sb[128 + j], bov = sb[192 + j];

    for (int t = 0; t < SEQ; t++) {
        float a0[4], a1[4], a2[4], a3[4];
        #pragma unroll
        for (int ei = 0; ei < 4; ei++) { a0[ei] = biv; a1[ei] = bfv; a2[ei] = bgv; a3[ei] = bov; }

        // x contribution (k = 0..15)
        #pragma unroll
        for (int k4 = 0; k4 < 4; k4++) {
            const float4 w0 = w0p[k4], w1 = w1p[k4], w2 = w2p[k4], w3 = w3p[k4];
            #pragma unroll
            for (int ei = 0; ei < 4; ei++) {
                const float4 v = ((const float4*)(sx + (eg * 4 + ei) * EMB))[k4];
                a0[ei] += w0.x * v.x; a0[ei] += w0.y * v.y; a0[ei] += w0.z * v.z; a0[ei] += w0.w * v.w;
                a1[ei] += w1.x * v.x; a1[ei] += w1.y * v.y; a1[ei] += w1.z * v.z; a1[ei] += w1.w * v.w;
                a2[ei] += w2.x * v.x; a2[ei] += w2.y * v.y; a2[ei] += w2.z * v.z; a2[ei] += w2.w * v.w;
                a3[ei] += w3.x * v.x; a3[ei] += w3.y * v.y; a3[ei] += w3.z * v.z; a3[ei] += w3.w * v.w;
            }
        }
        // h contribution (k = 16..79)
        #pragma unroll
        for (int k4 = 0; k4 < 16; k4++) {
            const float4 w0 = w0p[4 + k4], w1 = w1p[4 + k4], w2 = w2p[4 + k4], w3 = w3p[4 + k4];
            #pragma unroll
            for (int ei = 0; ei < 4; ei++) {
                const float4 v = ((const float4*)(sh + (eg * 4 + ei) * HSTRIDE))[k4];
                a0[ei] += w0.x * v.x; a0[ei] += w0.y * v.y; a0[ei] += w0.z * v.z; a0[ei] += w0.w * v.w;
                a1[ei] += w1.x * v.x; a1[ei] += w1.y * v.y; a1[ei] += w1.z * v.z; a1[ei] += w1.w * v.w;
                a2[ei] += w2.x * v.x; a2[ei] += w2.y * v.y; a2[ei] += w2.z * v.z; a2[ei] += w2.w * v.w;
                a3[ei] += w3.x * v.x; a3[ei] += w3.y * v.y; a3[ei] += w3.z * v.z; a3[ei] += w3.w * v.w;
            }
        }

        __syncthreads();   // all gate reads of sh/sx complete before overwriting

        #pragma unroll
        for (int ei = 0; ei < 4; ei++) {
            const int e = eg * 4 + ei;
            const float iv = sigmoidf_(a0[ei]);
            const float fv = sigmoidf_(a1[ei]);
            const float gv = tanh_fast(a2[ei]);
            const float ov = sigmoidf_(a3[ei]);
            const float cn = fv * sc[e * HSTRIDE + j] + iv * gv;
            sc[e * HSTRIDE + j] = cn;
            sh[e * HSTRIDE + j] = ov * tanh_fast(cn);
        }

        __syncthreads();   // h_new complete

        // rel_pos + next x embedding : warp 0 only, shfl avoids a 4th barrier
        if (tid < 32) {
            const int e = tid >> 1, d = tid & 1;
            const float* hv = sh + e * HSTRIDE;
            const float* wv = sWp + d * HDIM;
            float r0 = 0.f, r1 = 0.f, r2 = 0.f, r3 = 0.f;
            #pragma unroll
            for (int k = 0; k < HDIM; k += 4) {
                r0 += hv[k]     * wv[k];
                r1 += hv[k + 1] * wv[k + 1];
                r2 += hv[k + 2] * wv[k + 2];
                r3 += hv[k + 3] * wv[k + 3];
            }
            const float r = (r0 + r1) + (r2 + r3) + sbp[d];
            // pred_traj[e0+e][m][t][d]
            out[((e0 + e) * NMODE + m) * (SEQ * 2) + t * 2 + d] = r;

            const float ro   = __shfl_xor_sync(0xffffffffu, r, 1);
            const float rel0 = d ? ro : r;
            const float rel1 = d ? r  : ro;
            #pragma unroll
            for (int kk = 0; kk < 8; kk++) {
                const int k = d * 8 + kk;
                sx[e * EMB + k] = lrelu_(rel0 * sWe[k * 2] + rel1 * sWe[k * 2 + 1] + sbe[k]);
            }
        }
        __syncthreads();   // x_new visible before next step's gate reads
    }

    // stash final hidden state for confidence kernel
    for (int idx = tid; idx < TB * HDIM; idx += THREADS) {
        int e = idx >> 6, k = idx & 63;
        g_hfin[(m * NB + e0) * HDIM + idx] = sh[e * HSTRIDE + k];
    }
}

__global__ void conf_kernel(const float* __restrict__ Wc,
                            const float* __restrict__ bc,
                            float* __restrict__ out)
{
    const int e = blockIdx.x * blockDim.x + threadIdx.x;
    if (e >= NB) return;

    const float* pred = out + e * (NMODE * SEQ * 2);
    float l0 = bc[0], l1 = bc[1], l2 = bc[2];

    #pragma unroll
    for (int m = 0; m < NMODE; m++) {
        const int   base = m * (SEQ * 2 + HDIM);   // m * 124
        const float* w0 = Wc + 0 * 372 + base;
        const float* w1 = Wc + 1 * 372 + base;
        const float* w2 = Wc + 2 * 372 + base;
        const float* pm = pred + m * (SEQ * 2);
        #pragma unroll 4
        for (int i = 0; i < SEQ * 2; i++) {
            const float v = pm[i];
            l0 += w0[i] * v; l1 += w1[i] * v; l2 += w2[i] * v;
        }
        const float* hf = g_hfin + (m * NB + e) * HDIM;
        #pragma unroll 4
        for (int k = 0; k < HDIM; k++) {
            const float v = hf[k];
            l0 += w0[SEQ * 2 + k] * v; l1 += w1[SEQ * 2 + k] * v; l2 += w2[SEQ * 2 + k] * v;
        }
    }
    const float mx = fmaxf(l0, fmaxf(l1, l2));
    const float x0 = __expf(l0 - mx), x1 = __expf(l1 - mx), x2 = __expf(l2 - mx);
    const float inv = __fdividef(1.0f, x0 + x1 + x2);
    float* cf = out + NB * (NMODE * SEQ * 2) + e * NMODE;
    cf[0] = x0 * inv; cf[1] = x1 * inv; cf[2] = x2 * inv;
}

extern "C" void kernel_launch(void* const* d_in, const int* in_sizes, int n_in,
                              void* d_out, int out_size)
{
    // metadata order: traj_abs, traj_rel, h0, c0, W_ih, W_hh, b_ih, b_hh,
    //                 We, be, Wp, bp, Wc, bc   (traj_abs unused by the math)
    const float* traj_rel = (const float*)d_in[1];
    const float* h0   = (const float*)d_in[2];
    const float* c0   = (const float*)d_in[3];
    const float* W_ih = (const float*)d_in[4];
    const float* W_hh = (const float*)d_in[5];
    const float* b_ih = (const float*)d_in[6];
    const float* b_hh = (const float*)d_in[7];
    const float* We   = (const float*)d_in[8];
    const float* be   = (const float*)d_in[9];
    const float* Wp   = (const float*)d_in[10];
    const float* bp   = (const float*)d_in[11];
    const float* Wc   = (const float*)d_in[12];
    const float* bc   = (const float*)d_in[13];
    float* out = (float*)d_out;

    cudaFuncSetAttribute(lstm_main,
                         cudaFuncAttributeMaxDynamicSharedMemorySize, SMEM_BYTES);

    lstm_main<<<NTILES, THREADS, SMEM_BYTES>>>(traj_rel, h0, c0, W_ih, W_hh,
                                               b_ih, b_hh, We, be, Wp, bp, out);
    conf_kernel<<<NB / 128, 128>>>(Wc, bc, out);
}

// round 2
// speedup vs baseline: 1.0025x; 1.0025x over previous
#include <cuda_runtime.h>
#include <cuda_bf16.h>

#define NB      16384
#define HDIM    64
#define EMB     16
#define SEQ     30
#define NMODE   3
#define TB      32          // elements per block tile
#define THREADS 256
#define WSTRIDE 84          // padded weight row (80 used) -> conflict-free LDS.128
#define HSTRIDE 68          // padded h/c row (64 used)
#define NTILES  (NB * NMODE / TB)   // 1536

// SMEM layout (floats)
#define OFF_SW   0
#define OFF_SB   (OFF_SW  + 256 * WSTRIDE)   // 21504
#define OFF_SH   (OFF_SB  + 256)             // 21760
#define OFF_SC   (OFF_SH  + TB * HSTRIDE)    // 23936
#define OFF_SX   (OFF_SC  + TB * HSTRIDE)    // 26112
#define OFF_SWP  (OFF_SX  + TB * EMB)        // 26624
#define OFF_SWE  (OFF_SWP + 2 * HDIM)        // 26752
#define OFF_SBE  (OFF_SWE + EMB * 2)         // 26784
#define OFF_SBP  (OFF_SBE + EMB)             // 26800
#define SMEM_FLOATS (OFF_SBP + 2)            // 26802
#define SMEM_BYTES  (SMEM_FLOATS * 4)        // 107208

__device__ float g_hfin[NMODE * NB * HDIM];  // final hidden states scratch

typedef unsigned long long u64;

__device__ __forceinline__ void fma2(u64& acc, u64 a, u64 b) {
    asm("fma.rn.f32x2 %0, %1, %2, %0;" : "+l"(acc) : "l"(a), "l"(b));
}
__device__ __forceinline__ float hadd2(u64 a) {
    float lo, hi;
    asm("mov.b64 {%0,%1}, %2;" : "=f"(lo), "=f"(hi) : "l"(a));
    return lo + hi;
}
__device__ __forceinline__ u64 packf2(float lo, float hi) {
    u64 r;
    asm("mov.b64 %0, {%1,%2};" : "=l"(r) : "f"(lo), "f"(hi));
    return r;
}
__device__ __forceinline__ float sigmoidf_(float x) {
    return __fdividef(1.0f, 1.0f + __expf(-x));
}
__device__ __forceinline__ float tanh_fast(float x) {
    return __fdividef(2.0f, 1.0f + __expf(-2.0f * x)) - 1.0f;
}
__device__ __forceinline__ float lrelu_(float x) {
    return x > 0.0f ? x : 0.01f * x;
}

__global__ void __launch_bounds__(THREADS, 1)
lstm_main(const float* __restrict__ traj_rel,
          const float* __restrict__ h0,
          const float* __restrict__ c0,
          const float* __restrict__ W_ih,
          const float* __restrict__ W_hh,
          const float* __restrict__ b_ih,
          const float* __restrict__ b_hh,
          const float* __restrict__ We,
          const float* __restrict__ be,
          const float* __restrict__ Wp,
          const float* __restrict__ bp,
          float* __restrict__ out)
{
    extern __shared__ float smem[];
    float* sW  = smem + OFF_SW;    // [256][WSTRIDE]: gate row g, cols 0..15 W_ih, 16..79 W_hh
    float* sb  = smem + OFF_SB;    // [256]
    float* sh  = smem + OFF_SH;    // [TB][HSTRIDE]
    float* sc  = smem + OFF_SC;    // [TB][HSTRIDE]
    float* sx  = smem + OFF_SX;    // [TB][EMB]
    float* sWp = smem + OFF_SWP;   // [2][64]
    float* sWe = smem + OFF_SWE;   // [16][2]
    float* sbe = smem + OFF_SBE;   // [16]
    float* sbp = smem + OFF_SBP;   // [2]

    const int tid  = threadIdx.x;
    const int tile = blockIdx.x;          // 0..1535
    const int m    = tile >> 9;           // mode (512 tiles per mode)
    const int e0   = (tile & 511) * TB;   // first element of tile

    // ---- cooperative loads ----
    for (int idx = tid; idx < 256 * 80; idx += THREADS) {
        int g = idx / 80;
        int k = idx - g * 80;
        sW[g * WSTRIDE + k] = (k < EMB) ? W_ih[g * EMB + k]
                                        : W_hh[g * HDIM + (k - EMB)];
    }
    sb[tid] = b_ih[tid] + b_hh[tid];
    if (tid < 2 * HDIM) sWp[tid] = Wp[m * 2 * HDIM + tid];
    if (tid < EMB * 2)  sWe[tid] = We[tid];
    if (tid < EMB)      sbe[tid] = be[tid];
    if (tid < 2)        sbp[tid] = bp[m * 2 + tid];
    for (int idx = tid; idx < TB * HDIM; idx += THREADS) {
        int e = idx >> 6, k = idx & 63;
        sh[e * HSTRIDE + k] = h0[e0 * HDIM + idx];
        sc[e * HSTRIDE + k] = c0[e0 * HDIM + idx];
    }
    // x0 = leaky_relu(traj_rel @ We^T + be) : 32 elems x 16 dims = 512 items
    for (int idx = tid; idx < TB * EMB; idx += THREADS) {
        int e = idx >> 4, k = idx & 15;
        float t0 = traj_rel[(e0 + e) * 2 + 0];
        float t1 = traj_rel[(e0 + e) * 2 + 1];
        sx[e * EMB + k] = lrelu_(t0 * We[k * 2 + 0] + t1 * We[k * 2 + 1] + be[k]);
    }
    __syncthreads();

    const int j     = tid & 63;   // hidden unit
    const int eg    = tid >> 6;   // element group
    const int ebase = eg * 8;     // first of this thread's 8 elements

    const ulonglong2* w0p = (const ulonglong2*)(sW + (      j) * WSTRIDE);  // i
    const ulonglong2* w1p = (const ulonglong2*)(sW + ( 64 + j) * WSTRIDE);  // f
    const ulonglong2* w2p = (const ulonglong2*)(sW + (128 + j) * WSTRIDE);  // g
    const ulonglong2* w3p = (const ulonglong2*)(sW + (192 + j) * WSTRIDE);  // o
    // bias folded into packed accumulator init: (bias, 0)
    const u64 bi2 = packf2(sb[j],       0.0f);
    const u64 bf2 = packf2(sb[64 + j],  0.0f);
    const u64 bg2 = packf2(sb[128 + j], 0.0f);
    const u64 bo2 = packf2(sb[192 + j], 0.0f);

    for (int t = 0; t < SEQ; t++) {
        u64 a0[8], a1[8], a2[8], a3[8];
        #pragma unroll
        for (int e = 0; e < 8; e++) { a0[e] = bi2; a1[e] = bf2; a2[e] = bg2; a3[e] = bo2; }

        // x contribution (k = 0..15): 4 float4 rows -> 2 packed pairs each
        #pragma unroll
        for (int k4 = 0; k4 < 4; k4++) {
            const ulonglong2 w0 = w0p[k4], w1 = w1p[k4], w2 = w2p[k4], w3 = w3p[k4];
            #pragma unroll
            for (int e = 0; e < 8; e++) {
                const ulonglong2 v = ((const ulonglong2*)(sx + (ebase + e) * EMB))[k4];
                fma2(a0[e], v.x, w0.x); fma2(a0[e], v.y, w0.y);
                fma2(a1[e], v.x, w1.x); fma2(a1[e], v.y, w1.y);
                fma2(a2[e], v.x, w2.x); fma2(a2[e], v.y, w2.y);
                fma2(a3[e], v.x, w3.x); fma2(a3[e], v.y, w3.y);
            }
        }
        // h contribution (k = 16..79)
        #pragma unroll
        for (int k4 = 0; k4 < 16; k4++) {
            const ulonglong2 w0 = w0p[4 + k4], w1 = w1p[4 + k4],
                             w2 = w2p[4 + k4], w3 = w3p[4 + k4];
            #pragma unroll
            for (int e = 0; e < 8; e++) {
                const ulonglong2 v = ((const ulonglong2*)(sh + (ebase + e) * HSTRIDE))[k4];
                fma2(a0[e], v.x, w0.x); fma2(a0[e], v.y, w0.y);
                fma2(a1[e], v.x, w1.x); fma2(a1[e], v.y, w1.y);
                fma2(a2[e], v.x, w2.x); fma2(a2[e], v.y, w2.y);
                fma2(a3[e], v.x, w3.x); fma2(a3[e], v.y, w3.y);
            }
        }

        __syncthreads();   // gate reads of sh/sx complete before overwrite

        #pragma unroll
        for (int e = 0; e < 8; e++) {
            const int el = ebase + e;
            const float iv = sigmoidf_(hadd2(a0[e]));
            const float fv = sigmoidf_(hadd2(a1[e]));
            const float gv = tanh_fast(hadd2(a2[e]));
            const float ov = sigmoidf_(hadd2(a3[e]));
            const float cn = fv * sc[el * HSTRIDE + j] + iv * gv;
            sc[el * HSTRIDE + j] = cn;
            sh[el * HSTRIDE + j] = ov * tanh_fast(cn);
        }

        __syncthreads();   // h_new complete

        // rel_pos + next x embedding: 2 warps (64 threads = 32 elems x 2 dims)
        if (tid < 2 * TB) {
            const int e = tid >> 1, d = tid & 1;
            const float* hv = sh + e * HSTRIDE;
            const float* wv = sWp + d * HDIM;
            float r0 = 0.f, r1 = 0.f, r2 = 0.f, r3 = 0.f;
            #pragma unroll
            for (int k = 0; k < HDIM; k += 4) {
                r0 += hv[k]     * wv[k];
                r1 += hv[k + 1] * wv[k + 1];
                r2 += hv[k + 2] * wv[k + 2];
                r3 += hv[k + 3] * wv[k + 3];
            }
            const float r = (r0 + r1) + (r2 + r3) + sbp[d];
            out[((e0 + e) * NMODE + m) * (SEQ * 2) + t * 2 + d] = r;

            const float ro   = __shfl_xor_sync(0xffffffffu, r, 1);
            const float rel0 = d ? ro : r;
            const float rel1 = d ? r  : ro;
            #pragma unroll
            for (int kk = 0; kk < 8; kk++) {
                const int k = d * 8 + kk;
                sx[e * EMB + k] = lrelu_(rel0 * sWe[k * 2] + rel1 * sWe[k * 2 + 1] + sbe[k]);
            }
        }
        __syncthreads();   // x_new visible before next step
    }

    // stash final hidden state for confidence kernel
    for (int idx = tid; idx < TB * HDIM; idx += THREADS) {
        int e = idx >> 6, k = idx & 63;
        g_hfin[(m * NB + e0) * HDIM + idx] = sh[e * HSTRIDE + k];
    }
}

// Warp-cooperative confidence kernel: lanes stride the 372-dim dot products
// so global loads coalesce; 3 logits reduced via shfl.
#define CONF_EPW 16   // elements per warp
__global__ void __launch_bounds__(128)
conf_kernel(const float* __restrict__ Wc,
            const float* __restrict__ bc,
            float* __restrict__ out)
{
    const int warp = (blockIdx.x * blockDim.x + threadIdx.x) >> 5;
    const int lane = threadIdx.x & 31;
    const int ebase = warp * CONF_EPW;

    for (int ei = 0; ei < CONF_EPW; ei++) {
        const int e = ebase + ei;
        float l0 = 0.f, l1 = 0.f, l2 = 0.f;
        // conf_input[k], k = lane + 32*i, layout per mode: 60 pred then 64 hfin
        #pragma unroll
        for (int i = 0; i < 12; i++) {
            const int k = lane + 32 * i;
            if (k < 372) {
                const int q = (k >= 248) ? 2 : (k >= 124 ? 1 : 0);
                const int r = k - q * 124;
                const float v = (r < 60)
                    ? out[e * (NMODE * SEQ * 2) + q * 60 + r]
                    : g_hfin[(q * NB + e) * HDIM + (r - 60)];
                l0 += Wc[0 * 372 + k] * v;
                l1 += Wc[1 * 372 + k] * v;
                l2 += Wc[2 * 372 + k] * v;
            }
        }
        #pragma unroll
        for (int s = 16; s > 0; s >>= 1) {
            l0 += __shfl_xor_sync(0xffffffffu, l0, s);
            l1 += __shfl_xor_sync(0xffffffffu, l1, s);
            l2 += __shfl_xor_sync(0xffffffffu, l2, s);
        }
        if (lane == 0) {
            l0 += bc[0]; l1 += bc[1]; l2 += bc[2];
            const float mx = fmaxf(l0, fmaxf(l1, l2));
            const float x0 = __expf(l0 - mx), x1 = __expf(l1 - mx), x2 = __expf(l2 - mx);
            const float inv = __fdividef(1.0f, x0 + x1 + x2);
            float* cf = out + NB * (NMODE * SEQ * 2) + e * NMODE;
            cf[0] = x0 * inv; cf[1] = x1 * inv; cf[2] = x2 * inv;
        }
    }
}

extern "C" void kernel_launch(void* const* d_in, const int* in_sizes, int n_in,
                              void* d_out, int out_size)
{
    const float* traj_rel = (const float*)d_in[1];
    const float* h0   = (const float*)d_in[2];
    const float* c0   = (const float*)d_in[3];
    const float* W_ih = (const float*)d_in[4];
    const float* W_hh = (const float*)d_in[5];
    const float* b_ih = (const float*)d_in[6];
    const float* b_hh = (const float*)d_in[7];
    const float* We   = (const float*)d_in[8];
    const float* be   = (const float*)d_in[9];
    const float* Wp   = (const float*)d_in[10];
    const float* bp   = (const float*)d_in[11];
    const float* Wc   = (const float*)d_in[12];
    const float* bc   = (const float*)d_in[13];
    float* out = (float*)d_out;

    cudaFuncSetAttribute(lstm_main,
                         cudaFuncAttributeMaxDynamicSharedMemorySize, SMEM_BYTES);

    lstm_main<<<NTILES, THREADS, SMEM_BYTES>>>(traj_rel, h0, c0, W_ih, W_hh,
                                               b_ih, b_hh, We, be, Wp, bp, out);
    // NB elems, 16 per warp, 4 warps per block -> 256 blocks
    conf_kernel<<<NB / (CONF_EPW * 4), 128>>>(Wc, bc, out);
}

// round 3
// speedup vs baseline: 1.0035x; 1.0010x over previous
#include <cuda_runtime.h>
#include <cuda_bf16.h>

#define NB      16384
#define HDIM    64
#define EMB     16
#define SEQ     30
#define NMODE   3
#define TB      32          // elements per block tile
#define THREADS 256
#define WSTRIDE 84          // padded weight row (80 used) -> conflict-free LDS.128
#define HSTRIDE 68          // padded h/c row (64 used)
#define NTILES  (NB * NMODE / TB)   // 1536

// SMEM layout (floats)
#define OFF_SW   0
#define OFF_SB   (OFF_SW  + 256 * WSTRIDE)   // 21504
#define OFF_SH   (OFF_SB  + 256)             // 21760
#define OFF_SC   (OFF_SH  + TB * HSTRIDE)    // 23936
#define OFF_SX   (OFF_SC  + TB * HSTRIDE)    // 26112
#define OFF_SWP  (OFF_SX  + TB * EMB)        // 26624
#define OFF_SWE  (OFF_SWP + 2 * HDIM)        // 26752
#define OFF_SBE  (OFF_SWE + EMB * 2)         // 26784
#define OFF_SBP  (OFF_SBE + EMB)             // 26800
#define SMEM_FLOATS (OFF_SBP + 2)            // 26802
#define SMEM_BYTES  (SMEM_FLOATS * 4)        // 107208

__device__ float g_hfin[NMODE * NB * HDIM];  // final hidden states scratch

typedef unsigned long long u64;

__device__ __forceinline__ void fma2(u64& acc, u64 a, u64 b) {
    asm("fma.rn.f32x2 %0, %1, %2, %0;" : "+l"(acc) : "l"(a), "l"(b));
}
__device__ __forceinline__ float hadd2(u64 a) {
    float lo, hi;
    asm("mov.b64 {%0,%1}, %2;" : "=f"(lo), "=f"(hi) : "l"(a));
    return lo + hi;
}
__device__ __forceinline__ u64 packf2(float lo, float hi) {
    u64 r;
    asm("mov.b64 %0, {%1,%2};" : "=l"(r) : "f"(lo), "f"(hi));
    return r;
}
__device__ __forceinline__ float sigmoidf_(float x) {
    return __fdividef(1.0f, 1.0f + __expf(-x));
}
__device__ __forceinline__ float tanh_fast(float x) {
    return __fdividef(2.0f, 1.0f + __expf(-2.0f * x)) - 1.0f;
}
__device__ __forceinline__ float lrelu_(float x) {
    return x > 0.0f ? x : 0.01f * x;
}

__global__ void __launch_bounds__(THREADS, 1)
lstm_main(const float* __restrict__ traj_rel,
          const float* __restrict__ h0,
          const float* __restrict__ c0,
          const float* __restrict__ W_ih,
          const float* __restrict__ W_hh,
          const float* __restrict__ b_ih,
          const float* __restrict__ b_hh,
          const float* __restrict__ We,
          const float* __restrict__ be,
          const float* __restrict__ Wp,
          const float* __restrict__ bp,
          float* __restrict__ out)
{
    extern __shared__ float smem[];
    float* sW  = smem + OFF_SW;    // [256][WSTRIDE]: gate row g, cols 0..15 W_ih, 16..79 W_hh
    float* sb  = smem + OFF_SB;    // [256]
    float* sh  = smem + OFF_SH;    // [TB][HSTRIDE]
    float* sc  = smem + OFF_SC;    // [TB][HSTRIDE]
    float* sx  = smem + OFF_SX;    // [TB][EMB]
    float* sWp = smem + OFF_SWP;   // [2][64]
    float* sWe = smem + OFF_SWE;   // [16][2]
    float* sbe = smem + OFF_SBE;   // [16]
    float* sbp = smem + OFF_SBP;   // [2]

    const int tid  = threadIdx.x;
    const int tile = blockIdx.x;          // 0..1535
    const int m    = tile >> 9;           // mode (512 tiles per mode)
    const int e0   = (tile & 511) * TB;   // first element of tile

    // ---- cooperative loads ----
    for (int idx = tid; idx < 256 * 80; idx += THREADS) {
        int g = idx / 80;
        int k = idx - g * 80;
        sW[g * WSTRIDE + k] = (k < EMB) ? W_ih[g * EMB + k]
                                        : W_hh[g * HDIM + (k - EMB)];
    }
    sb[tid] = b_ih[tid] + b_hh[tid];
    if (tid < 2 * HDIM) sWp[tid] = Wp[m * 2 * HDIM + tid];
    if (tid < EMB * 2)  sWe[tid] = We[tid];
    if (tid < EMB)      sbe[tid] = be[tid];
    if (tid < 2)        sbp[tid] = bp[m * 2 + tid];
    for (int idx = tid; idx < TB * HDIM; idx += THREADS) {
        int e = idx >> 6, k = idx & 63;
        sh[e * HSTRIDE + k] = h0[e0 * HDIM + idx];
        sc[e * HSTRIDE + k] = c0[e0 * HDIM + idx];
    }
    // x0 = leaky_relu(traj_rel @ We^T + be) : 32 elems x 16 dims = 512 items
    for (int idx = tid; idx < TB * EMB; idx += THREADS) {
        int e = idx >> 4, k = idx & 15;
        float t0 = traj_rel[(e0 + e) * 2 + 0];
        float t1 = traj_rel[(e0 + e) * 2 + 1];
        sx[e * EMB + k] = lrelu_(t0 * We[k * 2 + 0] + t1 * We[k * 2 + 1] + be[k]);
    }
    __syncthreads();

    const int j     = tid & 63;   // hidden unit
    const int eg    = tid >> 6;   // element group
    const int ebase = eg * 8;     // first of this thread's 8 elements

    const ulonglong2* w0p = (const ulonglong2*)(sW + (      j) * WSTRIDE);  // i
    const ulonglong2* w1p = (const ulonglong2*)(sW + ( 64 + j) * WSTRIDE);  // f
    const ulonglong2* w2p = (const ulonglong2*)(sW + (128 + j) * WSTRIDE);  // g
    const ulonglong2* w3p = (const ulonglong2*)(sW + (192 + j) * WSTRIDE);  // o
    // bias folded into packed accumulator init: (bias, 0)
    const u64 bi2 = packf2(sb[j],       0.0f);
    const u64 bf2 = packf2(sb[64 + j],  0.0f);
    const u64 bg2 = packf2(sb[128 + j], 0.0f);
    const u64 bo2 = packf2(sb[192 + j], 0.0f);

    for (int t = 0; t < SEQ; t++) {
        u64 a0[8], a1[8], a2[8], a3[8];
        #pragma unroll
        for (int e = 0; e < 8; e++) { a0[e] = bi2; a1[e] = bf2; a2[e] = bg2; a3[e] = bo2; }

        // x contribution (k = 0..15): 4 float4 rows -> 2 packed pairs each
        #pragma unroll
        for (int k4 = 0; k4 < 4; k4++) {
            const ulonglong2 w0 = w0p[k4], w1 = w1p[k4], w2 = w2p[k4], w3 = w3p[k4];
            #pragma unroll
            for (int e = 0; e < 8; e++) {
                const ulonglong2 v = ((const ulonglong2*)(sx + (ebase + e) * EMB))[k4];
                fma2(a0[e], v.x, w0.x); fma2(a0[e], v.y, w0.y);
                fma2(a1[e], v.x, w1.x); fma2(a1[e], v.y, w1.y);
                fma2(a2[e], v.x, w2.x); fma2(a2[e], v.y, w2.y);
                fma2(a3[e], v.x, w3.x); fma2(a3[e], v.y, w3.y);
            }
        }
        // h contribution (k = 16..79)
        #pragma unroll
        for (int k4 = 0; k4 < 16; k4++) {
            const ulonglong2 w0 = w0p[4 + k4], w1 = w1p[4 + k4],
                             w2 = w2p[4 + k4], w3 = w3p[4 + k4];
            #pragma unroll
            for (int e = 0; e < 8; e++) {
                const ulonglong2 v = ((const ulonglong2*)(sh + (ebase + e) * HSTRIDE))[k4];
                fma2(a0[e], v.x, w0.x); fma2(a0[e], v.y, w0.y);
                fma2(a1[e], v.x, w1.x); fma2(a1[e], v.y, w1.y);
                fma2(a2[e], v.x, w2.x); fma2(a2[e], v.y, w2.y);
                fma2(a3[e], v.x, w3.x); fma2(a3[e], v.y, w3.y);
            }
        }

        __syncthreads();   // gate reads of sh/sx complete before overwrite

        #pragma unroll
        for (int e = 0; e < 8; e++) {
            const int el = ebase + e;
            const float iv = sigmoidf_(hadd2(a0[e]));
            const float fv = sigmoidf_(hadd2(a1[e]));
            const float gv = tanh_fast(hadd2(a2[e]));
            const float ov = sigmoidf_(hadd2(a3[e]));
            const float cn = fv * sc[el * HSTRIDE + j] + iv * gv;
            sc[el * HSTRIDE + j] = cn;
            sh[el * HSTRIDE + j] = ov * tanh_fast(cn);
        }

        __syncthreads();   // h_new complete

        // rel_pos + next x embedding: 2 warps (64 threads = 32 elems x 2 dims)
        if (tid < 2 * TB) {
            const int e = tid >> 1, d = tid & 1;
            const float* hv = sh + e * HSTRIDE;
            const float* wv = sWp + d * HDIM;
            float r0 = 0.f, r1 = 0.f, r2 = 0.f, r3 = 0.f;
            #pragma unroll
            for (int k = 0; k < HDIM; k += 4) {
                r0 += hv[k]     * wv[k];
                r1 += hv[k + 1] * wv[k + 1];
                r2 += hv[k + 2] * wv[k + 2];
                r3 += hv[k + 3] * wv[k + 3];
            }
            const float r = (r0 + r1) + (r2 + r3) + sbp[d];
            out[((e0 + e) * NMODE + m) * (SEQ * 2) + t * 2 + d] = r;

            const float ro   = __shfl_xor_sync(0xffffffffu, r, 1);
            const float rel0 = d ? ro : r;
            const float rel1 = d ? r  : ro;
            #pragma unroll
            for (int kk = 0; kk < 8; kk++) {
                const int k = d * 8 + kk;
                sx[e * EMB + k] = lrelu_(rel0 * sWe[k * 2] + rel1 * sWe[k * 2 + 1] + sbe[k]);
            }
        }
        __syncthreads();   // x_new visible before next step
    }

    // stash final hidden state for confidence kernel
    for (int idx = tid; idx < TB * HDIM; idx += THREADS) {
        int e = idx >> 6, k = idx & 63;
        g_hfin[(m * NB + e0) * HDIM + idx] = sh[e * HSTRIDE + k];
    }
}

// Warp-cooperative confidence kernel: lanes stride the 372-dim dot products
// so global loads coalesce; 3 logits reduced via shfl.
#define CONF_EPW 16   // elements per warp
__global__ void __launch_bounds__(128)
conf_kernel(const float* __restrict__ Wc,
            const float* __restrict__ bc,
            float* __restrict__ out)
{
    const int warp = (blockIdx.x * blockDim.x + threadIdx.x) >> 5;
    const int lane = threadIdx.x & 31;
    const int ebase = warp * CONF_EPW;

    for (int ei = 0; ei < CONF_EPW; ei++) {
        const int e = ebase + ei;
        float l0 = 0.f, l1 = 0.f, l2 = 0.f;
        // conf_input[k], k = lane + 32*i, layout per mode: 60 pred then 64 hfin
        #pragma unroll
        for (int i = 0; i < 12; i++) {
            const int k = lane + 32 * i;
            if (k < 372) {
                const int q = (k >= 248) ? 2 : (k >= 124 ? 1 : 0);
                const int r = k - q * 124;
                const float v = (r < 60)
                    ? out[e * (NMODE * SEQ * 2) + q * 60 + r]
                    : g_hfin[(q * NB + e) * HDIM + (r - 60)];
                l0 += Wc[0 * 372 + k] * v;
                l1 += Wc[1 * 372 + k] * v;
                l2 += Wc[2 * 372 + k] * v;
            }
        }
        #pragma unroll
        for (int s = 16; s > 0; s >>= 1) {
            l0 += __shfl_xor_sync(0xffffffffu, l0, s);
            l1 += __shfl_xor_sync(0xffffffffu, l1, s);
            l2 += __shfl_xor_sync(0xffffffffu, l2, s);
        }
        if (lane == 0) {
            l0 += bc[0]; l1 += bc[1]; l2 += bc[2];
            const float mx = fmaxf(l0, fmaxf(l1, l2));
            const float x0 = __expf(l0 - mx), x1 = __expf(l1 - mx), x2 = __expf(l2 - mx);
            const float inv = __fdividef(1.0f, x0 + x1 + x2);
            float* cf = out + NB * (NMODE * SEQ * 2) + e * NMODE;
            cf[0] = x0 * inv; cf[1] = x1 * inv; cf[2] = x2 * inv;
        }
    }
}

extern "C" void kernel_launch(void* const* d_in, const int* in_sizes, int n_in,
                              void* d_out, int out_size)
{
    const float* traj_rel = (const float*)d_in[1];
    const float* h0   = (const float*)d_in[2];
    const float* c0   = (const float*)d_in[3];
    const float* W_ih = (const float*)d_in[4];
    const float* W_hh = (const float*)d_in[5];
    const float* b_ih = (const float*)d_in[6];
    const float* b_hh = (const float*)d_in[7];
    const float* We   = (const float*)d_in[8];
    const float* be   = (const float*)d_in[9];
    const float* Wp   = (const float*)d_in[10];
    const float* bp   = (const float*)d_in[11];
    const float* Wc   = (const float*)d_in[12];
    const float* bc   = (const float*)d_in[13];
    float* out = (float*)d_out;

    cudaFuncSetAttribute(lstm_main,
                         cudaFuncAttributeMaxDynamicSharedMemorySize, SMEM_BYTES);

    lstm_main<<<NTILES, THREADS, SMEM_BYTES>>>(traj_rel, h0, c0, W_ih, W_hh,
                                               b_ih, b_hh, We, be, Wp, bp, out);
    // NB elems, 16 per warp, 4 warps per block -> 256 blocks
    conf_kernel<<<NB / (CONF_EPW * 4), 128>>>(Wc, bc, out);
}

// round 5
// speedup vs baseline: 1.7091x; 1.7031x over previous
#include <cuda_runtime.h>
#include <cstdint>

#define NB      16384
#define HDIM    64
#define SEQ     30
#define NMODE   3
#define MROWS   128
#define THREADS 256
#define NCTAS   384          // 49152 (elem,mode) rows / 128
#define STR     100          // tile row stride in floats (conflict-free: 100 % 32 = 4)
#define KS      11           // k-steps of 8 covering cols 0..87 (x|h|bias|pad)

// ---- SMEM float offsets ----
#define OFF_AH  0                         // A_hi : 128 x STR
#define OFF_AL  (OFF_AH + MROWS * STR)    // A_lo : 128 x STR
#define OFF_B   (OFF_AL + MROWS * STR)    // B    : 256 x STR (gate-interleaved cols)
#define OFF_WP  (OFF_B  + 256 * STR)      // [2][64]
#define OFF_WE  (OFF_WP + 128)            // [16][2]
#define OFF_BE  (OFF_WE + 32)             // [16]
#define OFF_BP  (OFF_BE + 16)             // [2] (+2 pad)
#define OFF_RL  (OFF_BP + 4)              // [128][2]
#define SMEM_FLOATS (OFF_RL + 256)
#define SMEM_BYTES  (SMEM_FLOATS * 4)     // 206,560 B

__device__ float g_hfin[NMODE * NB * HDIM];

// ============================ helpers ============================
__device__ __forceinline__ uint32_t tf32r(float x) {
    uint32_t r; asm("cvt.rna.tf32.f32 %0, %1;" : "=r"(r) : "f"(x)); return r;
}
__device__ __forceinline__ void mma8(float& d0, float& d1, float& d2, float& d3,
                                     uint32_t a0, uint32_t a1, uint32_t a2, uint32_t a3,
                                     uint32_t b0, uint32_t b1) {
    asm volatile("mma.sync.aligned.m16n8k8.row.col.f32.tf32.tf32.f32 "
                 "{%0,%1,%2,%3}, {%4,%5,%6,%7}, {%8,%9}, {%0,%1,%2,%3};"
                 : "+f"(d0), "+f"(d1), "+f"(d2), "+f"(d3)
                 : "r"(a0), "r"(a1), "r"(a2), "r"(a3), "r"(b0), "r"(b1));
}
__device__ __forceinline__ float sigf(float x) {
    return __fdividef(1.0f, 1.0f + __expf(-x));
}
__device__ __forceinline__ float tanhe(float x) {
    return __fdividef(2.0f, 1.0f + __expf(-2.0f * x)) - 1.0f;
}
__device__ __forceinline__ float lrelu_(float x) { return x > 0.0f ? x : 0.01f * x; }
__device__ __forceinline__ uint32_t fbits(float x) { return __float_as_uint(x); }

// ============================ main kernel ============================
__global__ void __launch_bounds__(THREADS, 1)
lstm_mma(const float* __restrict__ traj_rel, const float* __restrict__ h0,
         const float* __restrict__ c0,       const float* __restrict__ W_ih,
         const float* __restrict__ W_hh,     const float* __restrict__ b_ih,
         const float* __restrict__ b_hh,     const float* __restrict__ We,
         const float* __restrict__ be,       const float* __restrict__ Wp,
         const float* __restrict__ bp,       float* __restrict__ out)
{
    extern __shared__ float sm[];
    float* sAH = sm + OFF_AH;
    float* sAL = sm + OFF_AL;
    float* sB  = sm + OFF_B;
    float* sWp = sm + OFF_WP;
    float* sWe = sm + OFF_WE;
    float* sbe = sm + OFF_BE;
    float* sbp = sm + OFF_BP;
    float* sRL = sm + OFF_RL;

    const int tid  = threadIdx.x;
    const int w    = tid >> 5;
    const int lane = tid & 31;
    const int g    = lane >> 2;        // mma group id (fragment row within tile)
    const int tig  = lane & 3;         // thread-in-group
    const int rA   = 16 * w + g;       // fragment base row (a0/a2); a1/a3 use rA+8
    const int row  = rA + 8 * (tig & 1);   // the row this thread's epilogue owns
    const int usel = tig >> 1;             // unit offset within n-tile (0 or 1)
    const int m    = blockIdx.x >> 7;
    const int e0   = (blockIdx.x & 127) * MROWS;

    // ---- prologue: B = gate-interleaved [W_ih | W_hh | b | 0], tf32 ----
    // B column n = 4*unit + gate  <->  original W row = gate*64 + unit
    for (int idx = tid; idx < 256 * 88; idx += THREADS) {
        int n = idx / 88, k = idx - n * 88;
        int u = n >> 2, gate = n & 3, wr = gate * 64 + u;
        float v = (k < 16)  ? W_ih[wr * 16 + k]
                : (k < 80)  ? W_hh[wr * 64 + (k - 16)]
                : (k == 80) ? (b_ih[wr] + b_hh[wr]) : 0.0f;
        sB[n * STR + k] = __uint_as_float(tf32r(v));
    }
    // ---- prologue: A = [x0 | h0 | 1 | 0] split into hi/lo tf32 ----
    for (int idx = tid; idx < MROWS * 88; idx += THREADS) {
        int r = idx / 88, k = idx - r * 88;
        float v;
        if (k < 16) {
            float t0 = traj_rel[(e0 + r) * 2 + 0];
            float t1 = traj_rel[(e0 + r) * 2 + 1];
            v = lrelu_(t0 * We[k * 2 + 0] + t1 * We[k * 2 + 1] + be[k]);
        } else if (k < 80) v = h0[(e0 + r) * HDIM + (k - 16)];
        else               v = (k == 80) ? 1.0f : 0.0f;
        uint32_t hb = tf32r(v);
        sAH[r * STR + k] = __uint_as_float(hb);
        sAL[r * STR + k] = __uint_as_float(tf32r(v - __uint_as_float(hb)));
    }
    if (tid < 128) sWp[tid] = Wp[m * 128 + tid];   // [d][u]
    if (tid < 32)  sWe[tid] = We[tid];
    if (tid < 16)  sbe[tid] = be[tid];
    if (tid < 2)   sbp[tid] = bp[m * 2 + tid];

    // per-thread cell state: (row, unit = 2*nt + usel)
    float c[32];
    #pragma unroll
    for (int nt = 0; nt < 32; nt++)
        c[nt] = c0[(e0 + row) * HDIM + 2 * nt + usel];

    __syncthreads();

    for (int t = 0; t < SEQ; t++) {
        // ---- load A fragments (hi: 11 k-steps, lo: 10; lo cols 80..87 are 0) ----
        uint32_t ah[KS][4], al[KS - 1][4];
        #pragma unroll
        for (int ks = 0; ks < KS; ks++) {
            int k0 = ks * 8;
            ah[ks][0] = fbits(sAH[rA * STR + k0 + tig]);
            ah[ks][1] = fbits(sAH[(rA + 8) * STR + k0 + tig]);
            ah[ks][2] = fbits(sAH[rA * STR + k0 + tig + 4]);
            ah[ks][3] = fbits(sAH[(rA + 8) * STR + k0 + tig + 4]);
            if (ks < KS - 1) {
                al[ks][0] = fbits(sAL[rA * STR + k0 + tig]);
                al[ks][1] = fbits(sAL[(rA + 8) * STR + k0 + tig]);
                al[ks][2] = fbits(sAL[rA * STR + k0 + tig + 4]);
                al[ks][3] = fbits(sAL[(rA + 8) * STR + k0 + tig + 4]);
            }
        }
        __syncthreads();   // all warps hold frags; sA h-region now writable

        float p0 = 0.0f, p1 = 0.0f;

        // ---- n-tiles in pairs: 4 independent accumulator chains ----
        #pragma unroll
        for (int nt2 = 0; nt2 < 16; nt2++) {
            const float* bbA = sB + (16 * nt2 + g) * STR + tig;
            const float* bbB = bbA + 8 * STR;
            float dA0 = 0, dA1 = 0, dA2 = 0, dA3 = 0;   // hi chain, tile 2*nt2
            float eA0 = 0, eA1 = 0, eA2 = 0, eA3 = 0;   // lo chain
            float dB0 = 0, dB1 = 0, dB2 = 0, dB3 = 0;   // hi chain, tile 2*nt2+1
            float eB0 = 0, eB1 = 0, eB2 = 0, eB3 = 0;
            #pragma unroll
            for (int ks = 0; ks < KS; ks++) {
                uint32_t bA0 = fbits(bbA[ks * 8]), bA1 = fbits(bbA[ks * 8 + 4]);
                uint32_t bB0 = fbits(bbB[ks * 8]), bB1 = fbits(bbB[ks * 8 + 4]);
                mma8(dA0, dA1, dA2, dA3, ah[ks][0], ah[ks][1], ah[ks][2], ah[ks][3], bA0, bA1);
                mma8(dB0, dB1, dB2, dB3, ah[ks][0], ah[ks][1], ah[ks][2], ah[ks][3], bB0, bB1);
                if (ks < KS - 1) {
                    mma8(eA0, eA1, eA2, eA3, al[ks][0], al[ks][1], al[ks][2], al[ks][3], bA0, bA1);
                    mma8(eB0, eB1, eB2, eB3, al[ks][0], al[ks][1], al[ks][2], al[ks][3], bB0, bB1);
                }
            }
            dA0 += eA0; dA1 += eA1; dA2 += eA2; dA3 += eA3;
            dB0 += eB0; dB1 += eB1; dB2 += eB2; dB3 += eB3;

            // ---- epilogue for the two tiles ----
            #pragma unroll
            for (int half = 0; half < 2; half++) {
                const int   nt = 2 * nt2 + half;
                const float d0 = half ? dB0 : dA0, d1 = half ? dB1 : dA1;
                const float d2 = half ? dB2 : dA2, d3 = half ? dB3 : dA3;
                // exchange: even lane%2 keeps row rA (i,f), odd keeps row rA+8 (g,o)
                const bool  odd = tig & 1;
                const float s0 = odd ? d0 : d2;
                const float s1 = odd ? d1 : d3;
                const float q0 = __shfl_xor_sync(0xffffffffu, s0, 1);
                const float q1 = __shfl_xor_sync(0xffffffffu, s1, 1);
                const float gi = odd ? q0 : d0;
                const float gf = odd ? q1 : d1;
                const float gg = odd ? d2 : q0;
                const float go = odd ? d3 : q1;
                const float iv = sigf(gi);
                const float fv = sigf(gf);
                const float gv = tanhe(gg);
                const float ov = sigf(go);
                const float cn = fv * c[nt] + iv * gv;
                c[nt] = cn;
                const float h = ov * tanhe(cn);
                const int   u = 2 * nt + usel;
                p0 += h * sWp[u];
                p1 += h * sWp[64 + u];
                const uint32_t hb = tf32r(h);
                sAH[row * STR + 16 + u] = __uint_as_float(hb);
                sAL[row * STR + 16 + u] = __uint_as_float(tf32r(h - __uint_as_float(hb)));
                if (t == SEQ - 1)
                    g_hfin[(m * NB + e0 + row) * HDIM + u] = h;
            }
        }

        // ---- reduce rel_pos partials: (tig0,tig2) share row rA, (tig1,tig3) rA+8 ----
        p0 += __shfl_xor_sync(0xffffffffu, p0, 2);
        p1 += __shfl_xor_sync(0xffffffffu, p1, 2);
        if (tig < 2) { sRL[row * 2 + 0] = p0; sRL[row * 2 + 1] = p1; }
        __syncthreads();

        // ---- rel_pos out + next x embedding (thread -> row=tid>>1, d=tid&1) ----
        {
            const int r2 = tid >> 1, d = tid & 1;
            const float rel = sRL[r2 * 2 + d] + sbp[d];
            out[(e0 + r2) * (NMODE * SEQ * 2) + m * (SEQ * 2) + t * 2 + d] = rel;
            const float rot  = __shfl_xor_sync(0xffffffffu, rel, 1);
            const float rel0 = d ? rot : rel;
            const float rel1 = d ? rel : rot;
            float xh[8], xl[8];
            #pragma unroll
            for (int kk = 0; kk < 8; kk++) {
                const int k = d * 8 + kk;
                const float xv = lrelu_(rel0 * sWe[k * 2] + rel1 * sWe[k * 2 + 1] + sbe[k]);
                const uint32_t xb = tf32r(xv);
                xh[kk] = __uint_as_float(xb);
                xl[kk] = __uint_as_float(tf32r(xv - __uint_as_float(xb)));
            }
            *(float4*)(sAH + r2 * STR + d * 8)     = make_float4(xh[0], xh[1], xh[2], xh[3]);
            *(float4*)(sAH + r2 * STR + d * 8 + 4) = make_float4(xh[4], xh[5], xh[6], xh[7]);
            *(float4*)(sAL + r2 * STR + d * 8)     = make_float4(xl[0], xl[1], xl[2], xl[3]);
            *(float4*)(sAL + r2 * STR + d * 8 + 4) = make_float4(xl[4], xl[5], xl[6], xl[7]);
        }
        __syncthreads();
    }
}

// ============================ confidence kernel ============================
#define CONF_EPW 2
__global__ void __launch_bounds__(256)
conf_kernel(const float* __restrict__ Wc,
            const float* __restrict__ bc,
            float* __restrict__ out)
{
    const int warp  = (blockIdx.x * blockDim.x + threadIdx.x) >> 5;
    const int lane  = threadIdx.x & 31;
    const int ebase = warp * CONF_EPW;

    for (int ei = 0; ei < CONF_EPW; ei++) {
        const int e = ebase + ei;
        float l0 = 0.f, l1 = 0.f, l2 = 0.f;
        #pragma unroll
        for (int i = 0; i < 12; i++) {
            const int k = lane + 32 * i;
            if (k < 372) {
                const int q = (k >= 248) ? 2 : (k >= 124 ? 1 : 0);
                const int r = k - q * 124;
                const float v = (r < 60)
                    ? out[e * (NMODE * SEQ * 2) + q * 60 + r]
                    : g_hfin[(q * NB + e) * HDIM + (r - 60)];
                l0 += Wc[0 * 372 + k] * v;
                l1 += Wc[1 * 372 + k] * v;
                l2 += Wc[2 * 372 + k] * v;
            }
        }
        #pragma unroll
        for (int s = 16; s > 0; s >>= 1) {
            l0 += __shfl_xor_sync(0xffffffffu, l0, s);
            l1 += __shfl_xor_sync(0xffffffffu, l1, s);
            l2 += __shfl_xor_sync(0xffffffffu, l2, s);
        }
        if (lane == 0) {
            l0 += bc[0]; l1 += bc[1]; l2 += bc[2];
            const float mx = fmaxf(l0, fmaxf(l1, l2));
            const float x0 = __expf(l0 - mx), x1 = __expf(l1 - mx), x2 = __expf(l2 - mx);
            const float inv = __fdividef(1.0f, x0 + x1 + x2);
            float* cf = out + NB * (NMODE * SEQ * 2) + e * NMODE;
            cf[0] = x0 * inv; cf[1] = x1 * inv; cf[2] = x2 * inv;
        }
    }
}

extern "C" void kernel_launch(void* const* d_in, const int* in_sizes, int n_in,
                              void* d_out, int out_size)
{
    const float* traj_rel = (const float*)d_in[1];
    const float* h0   = (const float*)d_in[2];
    const float* c0   = (const float*)d_in[3];
    const float* W_ih = (const float*)d_in[4];
    const float* W_hh = (const float*)d_in[5];
    const float* b_ih = (const float*)d_in[6];
    const float* b_hh = (const float*)d_in[7];
    const float* We   = (const float*)d_in[8];
    const float* be   = (const float*)d_in[9];
    const float* Wp   = (const float*)d_in[10];
    const float* bp   = (const float*)d_in[11];
    const float* Wc   = (const float*)d_in[12];
    const float* bc   = (const float*)d_in[13];
    float* out = (float*)d_out;

    cudaFuncSetAttribute(lstm_mma,
                         cudaFuncAttributeMaxDynamicSharedMemorySize, SMEM_BYTES);

    lstm_mma<<<NCTAS, THREADS, SMEM_BYTES>>>(traj_rel, h0, c0, W_ih, W_hh,
                                             b_ih, b_hh, We, be, Wp, bp, out);
    conf_kernel<<<NB / (CONF_EPW * 8), 256>>>(Wc, bc, out);
}

// round 6
// speedup vs baseline: 2.3038x; 1.3480x over previous
#include <cuda_runtime.h>
#include <cstdint>

#define NB      16384
#define HDIM    64
#define SEQ     30
#define NMODE   3
#define MROWS   128
#define THREADS 256
#define NCTAS   384          // 49152 (elem,mode) rows / 128
#define STR     100          // A row stride in floats (conflict-free frag loads)
#define KS      11           // k-steps of 8 covering cols 0..87 (x|h|bias|pad)
#define NT      32           // n-tiles of 8 gate-interleaved columns

// ---- SMEM float offsets ----
#define OFF_BF  0                          // B fragments: NT*KS*32 lanes * 2 = 22528
#define OFF_AH  (OFF_BF + NT * KS * 64)    // A: 128 x STR = 12800
#define OFF_WP  (OFF_AH + MROWS * STR)     // [2][64]
#define OFF_WE  (OFF_WP + 128)             // [16][2]
#define OFF_BE  (OFF_WE + 32)              // [16]
#define OFF_BP  (OFF_BE + 16)              // [2] (+2 pad)
#define OFF_RL  (OFF_BP + 4)               // [128][2]
#define SMEM_FLOATS (OFF_RL + 256)
#define SMEM_BYTES  (SMEM_FLOATS * 4)      // ~143 KB

__device__ float g_hfin[NMODE * NB * HDIM];

// ============================ helpers ============================
__device__ __forceinline__ uint32_t tf32r(float x) {
    uint32_t r; asm("cvt.rna.tf32.f32 %0, %1;" : "=r"(r) : "f"(x)); return r;
}
__device__ __forceinline__ void mma8(float& d0, float& d1, float& d2, float& d3,
                                     uint32_t a0, uint32_t a1, uint32_t a2, uint32_t a3,
                                     uint32_t b0, uint32_t b1) {
    asm volatile("mma.sync.aligned.m16n8k8.row.col.f32.tf32.tf32.f32 "
                 "{%0,%1,%2,%3}, {%4,%5,%6,%7}, {%8,%9}, {%0,%1,%2,%3};"
                 : "+f"(d0), "+f"(d1), "+f"(d2), "+f"(d3)
                 : "r"(a0), "r"(a1), "r"(a2), "r"(a3), "r"(b0), "r"(b1));
}
__device__ __forceinline__ float sigf(float x) {
    return __fdividef(1.0f, 1.0f + __expf(-x));
}
__device__ __forceinline__ float tanhe(float x) {
    return __fdividef(2.0f, 1.0f + __expf(-2.0f * x)) - 1.0f;
}
__device__ __forceinline__ float lrelu_(float x) { return x > 0.0f ? x : 0.01f * x; }
__device__ __forceinline__ uint32_t fbits(float x) { return __float_as_uint(x); }

// original W row value for gate-matrix row wr, k-col (x|h|bias|pad layout)
__device__ __forceinline__ float wval(const float* W_ih, const float* W_hh,
                                      const float* b_ih, const float* b_hh,
                                      int wr, int k) {
    if (k < 16)  return W_ih[wr * 16 + k];
    if (k < 80)  return W_hh[wr * 64 + (k - 16)];
    if (k == 80) return b_ih[wr] + b_hh[wr];
    return 0.0f;
}

// ============================ main kernel ============================
__global__ void __launch_bounds__(THREADS, 1)
lstm_mma(const float* __restrict__ traj_rel, const float* __restrict__ h0,
         const float* __restrict__ c0,       const float* __restrict__ W_ih,
         const float* __restrict__ W_hh,     const float* __restrict__ b_ih,
         const float* __restrict__ b_hh,     const float* __restrict__ We,
         const float* __restrict__ be,       const float* __restrict__ Wp,
         const float* __restrict__ bp,       float* __restrict__ out)
{
    extern __shared__ float sm[];
    float* sBF = sm + OFF_BF;
    float* sAH = sm + OFF_AH;
    float* sWp = sm + OFF_WP;
    float* sWe = sm + OFF_WE;
    float* sbe = sm + OFF_BE;
    float* sbp = sm + OFF_BP;
    float* sRL = sm + OFF_RL;

    const int tid  = threadIdx.x;
    const int w    = tid >> 5;
    const int lane = tid & 31;
    const int g    = lane >> 2;            // fragment group (row within tile)
    const int tig  = lane & 3;             // thread-in-group
    const int rA   = 16 * w + g;           // fragment rows rA / rA+8
    const int row  = rA + 8 * (tig & 1);   // the row this thread's epilogue owns
    const int usel = tig >> 1;             // unit offset within n-tile
    const int m    = blockIdx.x >> 7;
    const int e0   = (blockIdx.x & 127) * MROWS;

    // ---- prologue: B packed in fragment-major order (tf32) ----
    // entry idx = (nt*KS + ks)*32 + lane holds float2 {B[n][k], B[n][k+4]}
    //   n = nt*8 + g, k = ks*8 + tig; B column n = 4*unit + gate <-> W row gate*64+unit
    for (int idx = tid; idx < NT * KS * 32; idx += THREADS) {
        const int lane_ = idx & 31;
        const int rest  = idx >> 5;
        const int ks    = rest % KS, nt = rest / KS;
        const int n     = nt * 8 + (lane_ >> 2);
        const int k     = ks * 8 + (lane_ & 3);
        const int u     = n >> 2, gate = n & 3, wr = gate * 64 + u;
        sBF[idx * 2 + 0] = __uint_as_float(tf32r(wval(W_ih, W_hh, b_ih, b_hh, wr, k)));
        sBF[idx * 2 + 1] = __uint_as_float(tf32r(wval(W_ih, W_hh, b_ih, b_hh, wr, k + 4)));
    }
    // ---- prologue: A = [x0 | h0 | 1 | 0], tf32 ----
    for (int idx = tid; idx < MROWS * 88; idx += THREADS) {
        int r = idx / 88, k = idx - r * 88;
        float v;
        if (k < 16) {
            float t0 = traj_rel[(e0 + r) * 2 + 0];
            float t1 = traj_rel[(e0 + r) * 2 + 1];
            v = lrelu_(t0 * We[k * 2 + 0] + t1 * We[k * 2 + 1] + be[k]);
        } else if (k < 80) v = h0[(e0 + r) * HDIM + (k - 16)];
        else               v = (k == 80) ? 1.0f : 0.0f;
        sAH[r * STR + k] = __uint_as_float(tf32r(v));
    }
    if (tid < 128) sWp[tid] = Wp[m * 128 + tid];
    if (tid < 32)  sWe[tid] = We[tid];
    if (tid < 16)  sbe[tid] = be[tid];
    if (tid < 2)   sbp[tid] = bp[m * 2 + tid];

    // per-thread cell state: (row, unit = 2*nt + usel)
    float c[NT];
    #pragma unroll
    for (int nt = 0; nt < NT; nt++)
        c[nt] = c0[(e0 + row) * HDIM + 2 * nt + usel];

    __syncthreads();

    for (int t = 0; t < SEQ; t++) {
        // ---- load A fragments (11 k-steps) ----
        uint32_t ah[KS][4];
        #pragma unroll
        for (int ks = 0; ks < KS; ks++) {
            const int k0 = ks * 8;
            ah[ks][0] = fbits(sAH[rA * STR + k0 + tig]);
            ah[ks][1] = fbits(sAH[(rA + 8) * STR + k0 + tig]);
            ah[ks][2] = fbits(sAH[rA * STR + k0 + tig + 4]);
            ah[ks][3] = fbits(sAH[(rA + 8) * STR + k0 + tig + 4]);
        }
        __syncthreads();   // all warps hold frags; A h-region now writable

        float p0 = 0.0f, p1 = 0.0f;

        // ---- n-tiles in groups of 4: 4 independent accumulator chains ----
        #pragma unroll
        for (int nt4 = 0; nt4 < NT / 4; nt4++) {
            float d[4][4] = {{0,0,0,0},{0,0,0,0},{0,0,0,0},{0,0,0,0}};
            const float2* bf = (const float2*)sBF + (nt4 * 4 * KS) * 32 + lane;
            #pragma unroll
            for (int ks = 0; ks < KS; ks++) {
                #pragma unroll
                for (int i = 0; i < 4; i++) {
                    const float2 bv = bf[(i * KS + ks) * 32];
                    mma8(d[i][0], d[i][1], d[i][2], d[i][3],
                         ah[ks][0], ah[ks][1], ah[ks][2], ah[ks][3],
                         fbits(bv.x), fbits(bv.y));
                }
            }
            // ---- epilogue for the four tiles ----
            #pragma unroll
            for (int i = 0; i < 4; i++) {
                const int nt = nt4 * 4 + i;
                const float d0 = d[i][0], d1 = d[i][1], d2 = d[i][2], d3 = d[i][3];
                // exchange: even tig keeps row rA rows' (i,f); odd keeps rA+8's (g,o)
                const bool  odd = tig & 1;
                const float s0 = odd ? d0 : d2;
                const float s1 = odd ? d1 : d3;
                const float q0 = __shfl_xor_sync(0xffffffffu, s0, 1);
                const float q1 = __shfl_xor_sync(0xffffffffu, s1, 1);
                const float gi = odd ? q0 : d0;
                const float gf = odd ? q1 : d1;
                const float gg = odd ? d2 : q0;
                const float go = odd ? d3 : q1;
                const float iv = sigf(gi);
                const float fv = sigf(gf);
                const float gv = tanhe(gg);
                const float ov = sigf(go);
                const float cn = fv * c[nt] + iv * gv;
                c[nt] = cn;
                const float h = ov * tanhe(cn);
                const int   u = 2 * nt + usel;
                p0 += h * sWp[u];
                p1 += h * sWp[64 + u];
                sAH[row * STR + 16 + u] = __uint_as_float(tf32r(h));
                if (t == SEQ - 1)
                    g_hfin[(m * NB + e0 + row) * HDIM + u] = h;
            }
        }

        // ---- reduce rel_pos partials: lanes (tig, tig^2) share a row ----
        p0 += __shfl_xor_sync(0xffffffffu, p0, 2);
        p1 += __shfl_xor_sync(0xffffffffu, p1, 2);
        if (tig < 2) { sRL[row * 2 + 0] = p0; sRL[row * 2 + 1] = p1; }
        __syncthreads();

        // ---- rel_pos out + next x embedding (thread -> row=tid>>1, d=tid&1) ----
        {
            const int r2 = tid >> 1, d = tid & 1;
            const float rel = sRL[r2 * 2 + d] + sbp[d];
            out[(e0 + r2) * (NMODE * SEQ * 2) + m * (SEQ * 2) + t * 2 + d] = rel;
            const float rot  = __shfl_xor_sync(0xffffffffu, rel, 1);
            const float rel0 = d ? rot : rel;
            const float rel1 = d ? rel : rot;
            float xh[8];
            #pragma unroll
            for (int kk = 0; kk < 8; kk++) {
                const int k = d * 8 + kk;
                const float xv = lrelu_(rel0 * sWe[k * 2] + rel1 * sWe[k * 2 + 1] + sbe[k]);
                xh[kk] = __uint_as_float(tf32r(xv));
            }
            *(float4*)(sAH + r2 * STR + d * 8)     = make_float4(xh[0], xh[1], xh[2], xh[3]);
            *(float4*)(sAH + r2 * STR + d * 8 + 4) = make_float4(xh[4], xh[5], xh[6], xh[7]);
        }
        __syncthreads();
    }
}

// ============================ confidence kernel ============================
#define CONF_EPW 2
__global__ void __launch_bounds__(256)
conf_kernel(const float* __restrict__ Wc,
            const float* __restrict__ bc,
            float* __restrict__ out)
{
    const int warp  = (blockIdx.x * blockDim.x + threadIdx.x) >> 5;
    const int lane  = threadIdx.x & 31;
    const int ebase = warp * CONF_EPW;

    for (int ei = 0; ei < CONF_EPW; ei++) {
        const int e = ebase + ei;
        float l0 = 0.f, l1 = 0.f, l2 = 0.f;
        #pragma unroll
        for (int i = 0; i < 12; i++) {
            const int k = lane + 32 * i;
            if (k < 372) {
                const int q = (k >= 248) ? 2 : (k >= 124 ? 1 : 0);
                const int r = k - q * 124;
                const float v = (r < 60)
                    ? out[e * (NMODE * SEQ * 2) + q * 60 + r]
                    : g_hfin[(q * NB + e) * HDIM + (r - 60)];
                l0 += Wc[0 * 372 + k] * v;
                l1 += Wc[1 * 372 + k] * v;
                l2 += Wc[2 * 372 + k] * v;
            }
        }
        #pragma unroll
        for (int s = 16; s > 0; s >>= 1) {
            l0 += __shfl_xor_sync(0xffffffffu, l0, s);
            l1 += __shfl_xor_sync(0xffffffffu, l1, s);
            l2 += __shfl_xor_sync(0xffffffffu, l2, s);
        }
        if (lane == 0) {
            l0 += bc[0]; l1 += bc[1]; l2 += bc[2];
            const float mx = fmaxf(l0, fmaxf(l1, l2));
            const float x0 = __expf(l0 - mx), x1 = __expf(l1 - mx), x2 = __expf(l2 - mx);
            const float inv = __fdividef(1.0f, x0 + x1 + x2);
            float* cf = out + NB * (NMODE * SEQ * 2) + e * NMODE;
            cf[0] = x0 * inv; cf[1] = x1 * inv; cf[2] = x2 * inv;
        }
    }
}

extern "C" void kernel_launch(void* const* d_in, const int* in_sizes, int n_in,
                              void* d_out, int out_size)
{
    const float* traj_rel = (const float*)d_in[1];
    const float* h0   = (const float*)d_in[2];
    const float* c0   = (const float*)d_in[3];
    const float* W_ih = (const float*)d_in[4];
    const float* W_hh = (const float*)d_in[5];
    const float* b_ih = (const float*)d_in[6];
    const float* b_hh = (const float*)d_in[7];
    const float* We   = (const float*)d_in[8];
    const float* be   = (const float*)d_in[9];
    const float* Wp   = (const float*)d_in[10];
    const float* bp   = (const float*)d_in[11];
    const float* Wc   = (const float*)d_in[12];
    const float* bc   = (const float*)d_in[13];
    float* out = (float*)d_out;

    cudaFuncSetAttribute(lstm_mma,
                         cudaFuncAttributeMaxDynamicSharedMemorySize, SMEM_BYTES);

    lstm_mma<<<NCTAS, THREADS, SMEM_BYTES>>>(traj_rel, h0, c0, W_ih, W_hh,
                                             b_ih, b_hh, We, be, Wp, bp, out);
    conf_kernel<<<NB / (CONF_EPW * 8), 256>>>(Wc, bc, out);
}

// round 7
// speedup vs baseline: 3.4312x; 1.4894x over previous
#include <cuda_runtime.h>
#include <cuda_fp16.h>
#include <cstdint>

#define NB      16384
#define HDIM    64
#define SEQ     30
#define NMODE   3
#define MROWS   128
#define THREADS 256
#define NCTAS   384          // 49152 (elem,mode) rows / 128
#define STRH    88           // A row stride in halfs (44 words: conflict-free frags)
#define KS      5            // k-steps of 16 covering cols 0..79 (x16 | h64)
#define NT      32           // n-tiles of 8 gate-interleaved columns

// ---- SMEM float-unit offsets ----
#define OFF_BF  0                           // B frags: NT*KS*32 uint2 = 10240 floats
#define OFF_AH  (OFF_BF + NT * KS * 64)     // A halfs: 128*STRH = 11264 halfs = 5632 floats
#define OFF_BI  (OFF_AH + MROWS * STRH / 2) // [256] gate-interleaved bias
#define OFF_WP  (OFF_BI + 256)              // [2][64]
#define OFF_WE  (OFF_WP + 128)              // [16][2]
#define OFF_BE  (OFF_WE + 32)               // [16]
#define OFF_BP  (OFF_BE + 16)               // [2] (+2 pad)
#define OFF_RL  (OFF_BP + 4)                // [128][2]
#define SMEM_FLOATS (OFF_RL + 256)
#define SMEM_BYTES  (SMEM_FLOATS * 4)       // ~66.3 KB -> 2 CTAs/SM

__device__ float g_hfin[NMODE * NB * HDIM];

// ============================ helpers ============================
__device__ __forceinline__ void mma16(float& d0, float& d1, float& d2, float& d3,
                                      uint32_t a0, uint32_t a1, uint32_t a2, uint32_t a3,
                                      uint32_t b0, uint32_t b1) {
    asm volatile("mma.sync.aligned.m16n8k16.row.col.f32.f16.f16.f32 "
                 "{%0,%1,%2,%3}, {%4,%5,%6,%7}, {%8,%9}, {%0,%1,%2,%3};"
                 : "+f"(d0), "+f"(d1), "+f"(d2), "+f"(d3)
                 : "r"(a0), "r"(a1), "r"(a2), "r"(a3), "r"(b0), "r"(b1));
}
__device__ __forceinline__ float sigf(float x) {
    return __fdividef(1.0f, 1.0f + __expf(-x));
}
__device__ __forceinline__ float tanhe(float x) {
    return __fdividef(2.0f, 1.0f + __expf(-2.0f * x)) - 1.0f;
}
__device__ __forceinline__ float lrelu_(float x) { return x > 0.0f ? x : 0.01f * x; }

// gate-weight value for gate-matrix row wr, k-col in [x(16)|h(64)] layout
__device__ __forceinline__ float wval(const float* W_ih, const float* W_hh, int wr, int k) {
    return (k < 16) ? W_ih[wr * 16 + k] : W_hh[wr * 64 + (k - 16)];
}

// ============================ main kernel ============================
__global__ void __launch_bounds__(THREADS, 2)
lstm_mma(const float* __restrict__ traj_rel, const float* __restrict__ h0,
         const float* __restrict__ c0,       const float* __restrict__ W_ih,
         const float* __restrict__ W_hh,     const float* __restrict__ b_ih,
         const float* __restrict__ b_hh,     const float* __restrict__ We,
         const float* __restrict__ be,       const float* __restrict__ Wp,
         const float* __restrict__ bp,       float* __restrict__ out)
{
    extern __shared__ float sm[];
    float*  sBF = sm + OFF_BF;                  // fragment-major B (uint2 per entry)
    __half* sAh = (__half*)(sm + OFF_AH);       // A: [128][STRH] halfs
    float*  sBI = sm + OFF_BI;
    float*  sWp = sm + OFF_WP;
    float*  sWe = sm + OFF_WE;
    float*  sbe = sm + OFF_BE;
    float*  sbp = sm + OFF_BP;
    float*  sRL = sm + OFF_RL;

    const int tid  = threadIdx.x;
    const int w    = tid >> 5;
    const int lane = tid & 31;
    const int g    = lane >> 2;            // fragment group (row within m-tile)
    const int tig  = lane & 3;             // thread-in-group
    const int rA   = 16 * w + g;           // fragment rows rA / rA+8
    const int row  = rA + 8 * (tig & 1);   // row this thread's epilogue owns
    const int usel = tig >> 1;             // unit offset within n-tile
    const int m    = blockIdx.x >> 7;
    const int e0   = (blockIdx.x & 127) * MROWS;

    // ---- prologue: B fragments (f16), fragment-major ----
    // entry idx=(nt*KS+ks)*32+lane : uint2 { half2(B[n][k],B[n][k+1]),
    //                                        half2(B[n][k+8],B[n][k+9]) }
    //   n = nt*8 + (lane>>2), k = ks*16 + 2*(lane&3);  B col n=4u+gate <-> W row gate*64+u
    for (int idx = tid; idx < NT * KS * 32; idx += THREADS) {
        const int lane_ = idx & 31;
        const int rest  = idx >> 5;
        const int ks    = rest % KS, nt = rest / KS;
        const int n     = nt * 8 + (lane_ >> 2);
        const int k     = ks * 16 + 2 * (lane_ & 3);
        const int u     = n >> 2, gate = n & 3, wr = gate * 64 + u;
        __half2 lo = __floats2half2_rn(wval(W_ih, W_hh, wr, k),     wval(W_ih, W_hh, wr, k + 1));
        __half2 hi = __floats2half2_rn(wval(W_ih, W_hh, wr, k + 8), wval(W_ih, W_hh, wr, k + 9));
        ((uint2*)sBF)[idx] = make_uint2(*(uint32_t*)&lo, *(uint32_t*)&hi);
    }
    // ---- prologue: gate-interleaved bias, A = [x0 | h0] halfs ----
    if (tid < 256) {
        const int u = tid >> 2, gate = tid & 3, wr = gate * 64 + u;
        sBI[tid] = b_ih[wr] + b_hh[wr];
    }
    for (int idx = tid; idx < MROWS * 80; idx += THREADS) {
        const int r = idx / 80, k = idx - r * 80;
        float v;
        if (k < 16) {
            float t0 = traj_rel[(e0 + r) * 2 + 0];
            float t1 = traj_rel[(e0 + r) * 2 + 1];
            v = lrelu_(t0 * We[k * 2 + 0] + t1 * We[k * 2 + 1] + be[k]);
        } else v = h0[(e0 + r) * HDIM + (k - 16)];
        sAh[r * STRH + k] = __float2half_rn(v);
    }
    if (tid < 128) sWp[tid] = Wp[m * 128 + tid];
    if (tid < 32)  sWe[tid] = We[tid];
    if (tid < 16)  sbe[tid] = be[tid];
    if (tid < 2)   sbp[tid] = bp[m * 2 + tid];

    // per-thread cell state: (row, unit = 2*nt + usel)
    float c[NT];
    #pragma unroll
    for (int nt = 0; nt < NT; nt++)
        c[nt] = c0[(e0 + row) * HDIM + 2 * nt + usel];

    __syncthreads();

    for (int t = 0; t < SEQ; t++) {
        // ---- load A fragments (5 k-steps of 16) ----
        uint32_t ah[KS][4];
        #pragma unroll
        for (int ks = 0; ks < KS; ks++) {
            const int k0 = ks * 16 + 2 * tig;
            ah[ks][0] = *(const uint32_t*)(sAh + rA * STRH + k0);
            ah[ks][1] = *(const uint32_t*)(sAh + (rA + 8) * STRH + k0);
            ah[ks][2] = *(const uint32_t*)(sAh + rA * STRH + k0 + 8);
            ah[ks][3] = *(const uint32_t*)(sAh + (rA + 8) * STRH + k0 + 8);
        }
        __syncthreads();   // all warps hold frags; A writable

        float p0 = 0.0f, p1 = 0.0f;

        // ---- n-tiles in groups of 4: 4 independent accumulator chains ----
        #pragma unroll
        for (int nt4 = 0; nt4 < NT / 4; nt4++) {
            float d[4][4];
            #pragma unroll
            for (int i = 0; i < 4; i++) {    // bias init (cols n0=8*nt+2tig, n0+1)
                const float2 bv = *(const float2*)(sBI + (nt4 * 4 + i) * 8 + 2 * tig);
                d[i][0] = bv.x; d[i][1] = bv.y; d[i][2] = bv.x; d[i][3] = bv.y;
            }
            const uint2* bf = (const uint2*)sBF + (nt4 * 4 * KS) * 32 + lane;
            #pragma unroll
            for (int ks = 0; ks < KS; ks++) {
                #pragma unroll
                for (int i = 0; i < 4; i++) {
                    const uint2 bv = bf[(i * KS + ks) * 32];
                    mma16(d[i][0], d[i][1], d[i][2], d[i][3],
                          ah[ks][0], ah[ks][1], ah[ks][2], ah[ks][3],
                          bv.x, bv.y);
                }
            }
            // ---- epilogue for the four tiles ----
            #pragma unroll
            for (int i = 0; i < 4; i++) {
                const int nt = nt4 * 4 + i;
                const float d0 = d[i][0], d1 = d[i][1], d2 = d[i][2], d3 = d[i][3];
                // exchange: even tig keeps row rA's (i,f); odd keeps rA+8's (g,o)
                const bool  odd = tig & 1;
                const float s0 = odd ? d0 : d2;
                const float s1 = odd ? d1 : d3;
                const float q0 = __shfl_xor_sync(0xffffffffu, s0, 1);
                const float q1 = __shfl_xor_sync(0xffffffffu, s1, 1);
                const float gi = odd ? q0 : d0;
                const float gf = odd ? q1 : d1;
                const float gg = odd ? d2 : q0;
                const float go = odd ? d3 : q1;
                const float iv = sigf(gi);
                const float fv = sigf(gf);
                const float gv = tanhe(gg);
                const float ov = sigf(go);
                const float cn = fv * c[nt] + iv * gv;
                c[nt] = cn;
                const float h = ov * tanhe(cn);
                const int   u = 2 * nt + usel;
                p0 += h * sWp[u];
                p1 += h * sWp[64 + u];
                sAh[row * STRH + 16 + u] = __float2half_rn(h);
                if (t == SEQ - 1)
                    g_hfin[(m * NB + e0 + row) * HDIM + u] = h;
            }
        }

        // ---- reduce rel_pos partials: lanes (tig, tig^2) share a row ----
        p0 += __shfl_xor_sync(0xffffffffu, p0, 2);
        p1 += __shfl_xor_sync(0xffffffffu, p1, 2);
        if (tig < 2) { sRL[row * 2 + 0] = p0; sRL[row * 2 + 1] = p1; }
        __syncthreads();

        // ---- rel_pos out + next x embedding (thread -> row=tid>>1, d=tid&1) ----
        {
            const int r2 = tid >> 1, d = tid & 1;
            const float rel = sRL[r2 * 2 + d] + sbp[d];
            out[(e0 + r2) * (NMODE * SEQ * 2) + m * (SEQ * 2) + t * 2 + d] = rel;
            const float rot  = __shfl_xor_sync(0xffffffffu, rel, 1);
            const float rel0 = d ? rot : rel;
            const float rel1 = d ? rel : rot;
            __half xh[8];
            #pragma unroll
            for (int kk = 0; kk < 8; kk++) {
                const int k = d * 8 + kk;
                xh[kk] = __float2half_rn(lrelu_(rel0 * sWe[k * 2] + rel1 * sWe[k * 2 + 1] + sbe[k]));
            }
            *(uint4*)(sAh + r2 * STRH + d * 8) = *(uint4*)xh;   // 16B aligned: STRH*2=176, d*16
        }
        __syncthreads();
    }
}

// ============================ confidence kernel ============================
#define CONF_EPW 2
__global__ void __launch_bounds__(256)
conf_kernel(const float* __restrict__ Wc,
            const float* __restrict__ bc,
            float* __restrict__ out)
{
    const int warp  = (blockIdx.x * blockDim.x + threadIdx.x) >> 5;
    const int lane  = threadIdx.x & 31;
    const int ebase = warp * CONF_EPW;

    for (int ei = 0; ei < CONF_EPW; ei++) {
        const int e = ebase + ei;
        float l0 = 0.f, l1 = 0.f, l2 = 0.f;
        #pragma unroll
        for (int i = 0; i < 12; i++) {
            const int k = lane + 32 * i;
            if (k < 372) {
                const int q = (k >= 248) ? 2 : (k >= 124 ? 1 : 0);
                const int r = k - q * 124;
                const float v = (r < 60)
                    ? out[e * (NMODE * SEQ * 2) + q * 60 + r]
                    : g_hfin[(q * NB + e) * HDIM + (r - 60)];
                l0 += Wc[0 * 372 + k] * v;
                l1 += Wc[1 * 372 + k] * v;
                l2 += Wc[2 * 372 + k] * v;
            }
        }
        #pragma unroll
        for (int s = 16; s > 0; s >>= 1) {
            l0 += __shfl_xor_sync(0xffffffffu, l0, s);
            l1 += __shfl_xor_sync(0xffffffffu, l1, s);
            l2 += __shfl_xor_sync(0xffffffffu, l2, s);
        }
        if (lane == 0) {
            l0 += bc[0]; l1 += bc[1]; l2 += bc[2];
            const float mx = fmaxf(l0, fmaxf(l1, l2));
            const float x0 = __expf(l0 - mx), x1 = __expf(l1 - mx), x2 = __expf(l2 - mx);
            const float inv = __fdividef(1.0f, x0 + x1 + x2);
            float* cf = out + NB * (NMODE * SEQ * 2) + e * NMODE;
            cf[0] = x0 * inv; cf[1] = x1 * inv; cf[2] = x2 * inv;
        }
    }
}

extern "C" void kernel_launch(void* const* d_in, const int* in_sizes, int n_in,
                              void* d_out, int out_size)
{
    const float* traj_rel = (const float*)d_in[1];
    const float* h0   = (const float*)d_in[2];
    const float* c0   = (const float*)d_in[3];
    const float* W_ih = (const float*)d_in[4];
    const float* W_hh = (const float*)d_in[5];
    const float* b_ih = (const float*)d_in[6];
    const float* b_hh = (const float*)d_in[7];
    const float* We   = (const float*)d_in[8];
    const float* be   = (const float*)d_in[9];
    const float* Wp   = (const float*)d_in[10];
    const float* bp   = (const float*)d_in[11];
    const float* Wc   = (const float*)d_in[12];
    const float* bc   = (const float*)d_in[13];
    float* out = (float*)d_out;

    cudaFuncSetAttribute(lstm_mma,
                         cudaFuncAttributeMaxDynamicSharedMemorySize, SMEM_BYTES);

    lstm_mma<<<NCTAS, THREADS, SMEM_BYTES>>>(traj_rel, h0, c0, W_ih, W_hh,
                                             b_ih, b_hh, We, be, Wp, bp, out);
    conf_kernel<<<NB / (CONF_EPW * 8), 256>>>(Wc, bc, out);
}

// round 8
// speedup vs baseline: 4.8911x; 1.4255x over previous
#include <cuda_runtime.h>
#include <cuda_fp16.h>
#include <cstdint>

#define NB      16384
#define HDIM    64
#define SEQ     30
#define NMODE   3
#define MROWS   128
#define THREADS 256
#define NCTAS   384          // 49152 (elem,mode) rows / 128
#define STRH    88           // A row stride in halfs (44 words: conflict-free frags)
#define KS      5            // k-steps of 16 covering cols 0..79 (x16 | h64)
#define NT      32           // n-tiles of 8 gate-interleaved columns

// ---- SMEM float-unit offsets ----
#define OFF_BF  0                           // B frags: NT*KS*32 uint2 = 10240 floats
#define OFF_AH  (OFF_BF + NT * KS * 64)     // A halfs: 128*STRH = 11264 halfs = 5632 floats
#define OFF_BI  (OFF_AH + MROWS * STRH / 2) // [256] gate-interleaved bias
#define OFF_WP  (OFF_BI + 256)              // [2][64]
#define OFF_WE  (OFF_WP + 128)              // [16][2]
#define OFF_BE  (OFF_WE + 32)               // [16]
#define OFF_BP  (OFF_BE + 16)               // [2] (+2 pad)
#define OFF_RL  (OFF_BP + 4)                // [128][2]
#define SMEM_FLOATS (OFF_RL + 256)
#define SMEM_BYTES  (SMEM_FLOATS * 4)       // ~66.3 KB -> 2 CTAs/SM

__device__ float g_hfin[NMODE * NB * HDIM];

// ============================ helpers ============================
__device__ __forceinline__ void mma16(float& d0, float& d1, float& d2, float& d3,
                                      uint32_t a0, uint32_t a1, uint32_t a2, uint32_t a3,
                                      uint32_t b0, uint32_t b1) {
    asm volatile("mma.sync.aligned.m16n8k16.row.col.f32.f16.f16.f32 "
                 "{%0,%1,%2,%3}, {%4,%5,%6,%7}, {%8,%9}, {%0,%1,%2,%3};"
                 : "+f"(d0), "+f"(d1), "+f"(d2), "+f"(d3)
                 : "r"(a0), "r"(a1), "r"(a2), "r"(a3), "r"(b0), "r"(b1));
}
// single-MUFU tanh (MUFU.TANH, sm_75+)
__device__ __forceinline__ float tanha(float x) {
    float r; asm("tanh.approx.f32 %0, %1;" : "=f"(r) : "f"(x)); return r;
}
// sigmoid(x) = 0.5*tanh(0.5x) + 0.5  (1 MUFU + 2 FMA)
__device__ __forceinline__ float sigf(float x) {
    return fmaf(0.5f, tanha(0.5f * x), 0.5f);
}
__device__ __forceinline__ float lrelu_(float x) { return x > 0.0f ? x : 0.01f * x; }

// gate-weight value for gate-matrix row wr, k-col in [x(16)|h(64)] layout
__device__ __forceinline__ float wval(const float* W_ih, const float* W_hh, int wr, int k) {
    return (k < 16) ? W_ih[wr * 16 + k] : W_hh[wr * 64 + (k - 16)];
}

// ============================ main kernel ============================
__global__ void __launch_bounds__(THREADS, 2)
lstm_mma(const float* __restrict__ traj_rel, const float* __restrict__ h0,
         const float* __restrict__ c0,       const float* __restrict__ W_ih,
         const float* __restrict__ W_hh,     const float* __restrict__ b_ih,
         const float* __restrict__ b_hh,     const float* __restrict__ We,
         const float* __restrict__ be,       const float* __restrict__ Wp,
         const float* __restrict__ bp,       float* __restrict__ out)
{
    extern __shared__ float sm[];
    float*  sBF = sm + OFF_BF;                  // fragment-major B (uint2 per entry)
    __half* sAh = (__half*)(sm + OFF_AH);       // A: [128][STRH] halfs
    float*  sBI = sm + OFF_BI;
    float*  sWp = sm + OFF_WP;
    float*  sWe = sm + OFF_WE;
    float*  sbe = sm + OFF_BE;
    float*  sbp = sm + OFF_BP;
    float*  sRL = sm + OFF_RL;

    const int tid  = threadIdx.x;
    const int w    = tid >> 5;
    const int lane = tid & 31;
    const int g    = lane >> 2;            // fragment group (row within m-tile)
    const int tig  = lane & 3;             // thread-in-group
    const int rA   = 16 * w + g;           // fragment rows rA / rA+8
    const int row  = rA + 8 * (tig & 1);   // row this thread's epilogue owns
    const int usel = tig >> 1;             // unit offset within n-tile
    const int m    = blockIdx.x >> 7;
    const int e0   = (blockIdx.x & 127) * MROWS;

    // ---- prologue: B fragments (f16), fragment-major ----
    for (int idx = tid; idx < NT * KS * 32; idx += THREADS) {
        const int lane_ = idx & 31;
        const int rest  = idx >> 5;
        const int ks    = rest % KS, nt = rest / KS;
        const int n     = nt * 8 + (lane_ >> 2);
        const int k     = ks * 16 + 2 * (lane_ & 3);
        const int u     = n >> 2, gate = n & 3, wr = gate * 64 + u;
        __half2 lo = __floats2half2_rn(wval(W_ih, W_hh, wr, k),     wval(W_ih, W_hh, wr, k + 1));
        __half2 hi = __floats2half2_rn(wval(W_ih, W_hh, wr, k + 8), wval(W_ih, W_hh, wr, k + 9));
        ((uint2*)sBF)[idx] = make_uint2(*(uint32_t*)&lo, *(uint32_t*)&hi);
    }
    // ---- prologue: gate-interleaved bias, A = [x0 | h0] halfs ----
    if (tid < 256) {
        const int u = tid >> 2, gate = tid & 3, wr = gate * 64 + u;
        sBI[tid] = b_ih[wr] + b_hh[wr];
    }
    for (int idx = tid; idx < MROWS * 80; idx += THREADS) {
        const int r = idx / 80, k = idx - r * 80;
        float v;
        if (k < 16) {
            float t0 = traj_rel[(e0 + r) * 2 + 0];
            float t1 = traj_rel[(e0 + r) * 2 + 1];
            v = lrelu_(t0 * We[k * 2 + 0] + t1 * We[k * 2 + 1] + be[k]);
        } else v = h0[(e0 + r) * HDIM + (k - 16)];
        sAh[r * STRH + k] = __float2half_rn(v);
    }
    if (tid < 128) sWp[tid] = Wp[m * 128 + tid];
    if (tid < 32)  sWe[tid] = We[tid];
    if (tid < 16)  sbe[tid] = be[tid];
    if (tid < 2)   sbp[tid] = bp[m * 2 + tid];

    // per-thread cell state: (row, unit = 2*nt + usel)
    float c[NT];
    #pragma unroll
    for (int nt = 0; nt < NT; nt++)
        c[nt] = c0[(e0 + row) * HDIM + 2 * nt + usel];

    __syncthreads();

    for (int t = 0; t < SEQ; t++) {
        // ---- load A fragments (5 k-steps of 16) ----
        uint32_t ah[KS][4];
        #pragma unroll
        for (int ks = 0; ks < KS; ks++) {
            const int k0 = ks * 16 + 2 * tig;
            ah[ks][0] = *(const uint32_t*)(sAh + rA * STRH + k0);
            ah[ks][1] = *(const uint32_t*)(sAh + (rA + 8) * STRH + k0);
            ah[ks][2] = *(const uint32_t*)(sAh + rA * STRH + k0 + 8);
            ah[ks][3] = *(const uint32_t*)(sAh + (rA + 8) * STRH + k0 + 8);
        }
        __syncthreads();   // all warps hold frags; A writable

        float p0 = 0.0f, p1 = 0.0f;

        // ---- n-tiles in groups of 4: 4 independent accumulator chains ----
        #pragma unroll
        for (int nt4 = 0; nt4 < NT / 4; nt4++) {
            float d[4][4];
            #pragma unroll
            for (int i = 0; i < 4; i++) {    // bias init (cols n0=8*nt+2tig, n0+1)
                const float2 bv = *(const float2*)(sBI + (nt4 * 4 + i) * 8 + 2 * tig);
                d[i][0] = bv.x; d[i][1] = bv.y; d[i][2] = bv.x; d[i][3] = bv.y;
            }
            const uint2* bf = (const uint2*)sBF + (nt4 * 4 * KS) * 32 + lane;
            #pragma unroll
            for (int ks = 0; ks < KS; ks++) {
                #pragma unroll
                for (int i = 0; i < 4; i++) {
                    const uint2 bv = bf[(i * KS + ks) * 32];
                    mma16(d[i][0], d[i][1], d[i][2], d[i][3],
                          ah[ks][0], ah[ks][1], ah[ks][2], ah[ks][3],
                          bv.x, bv.y);
                }
            }
            // ---- epilogue for the four tiles ----
            #pragma unroll
            for (int i = 0; i < 4; i++) {
                const int nt = nt4 * 4 + i;
                const float d0 = d[i][0], d1 = d[i][1], d2 = d[i][2], d3 = d[i][3];
                // exchange: even tig keeps row rA's (i,f); odd keeps rA+8's (g,o)
                const bool  odd = tig & 1;
                const float s0 = odd ? d0 : d2;
                const float s1 = odd ? d1 : d3;
                const float q0 = __shfl_xor_sync(0xffffffffu, s0, 1);
                const float q1 = __shfl_xor_sync(0xffffffffu, s1, 1);
                const float gi = odd ? q0 : d0;
                const float gf = odd ? q1 : d1;
                const float gg = odd ? d2 : q0;
                const float go = odd ? d3 : q1;
                const float iv = sigf(gi);
                const float fv = sigf(gf);
                const float gv = tanha(gg);
                const float ov = sigf(go);
                const float cn = fv * c[nt] + iv * gv;
                c[nt] = cn;
                const float h = ov * tanha(cn);
                const int   u = 2 * nt + usel;
                p0 += h * sWp[u];
                p1 += h * sWp[64 + u];
                sAh[row * STRH + 16 + u] = __float2half_rn(h);
                if (t == SEQ - 1)
                    g_hfin[(m * NB + e0 + row) * HDIM + u] = h;
            }
        }

        // ---- reduce rel_pos partials: lanes (tig, tig^2) share a row ----
        p0 += __shfl_xor_sync(0xffffffffu, p0, 2);
        p1 += __shfl_xor_sync(0xffffffffu, p1, 2);
        if (tig < 2) { sRL[row * 2 + 0] = p0; sRL[row * 2 + 1] = p1; }
        __syncthreads();

        // ---- rel_pos out + next x embedding (thread -> row=tid>>1, d=tid&1) ----
        {
            const int r2 = tid >> 1, d = tid & 1;
            const float rel = sRL[r2 * 2 + d] + sbp[d];
            out[(e0 + r2) * (NMODE * SEQ * 2) + m * (SEQ * 2) + t * 2 + d] = rel;
            const float rot  = __shfl_xor_sync(0xffffffffu, rel, 1);
            const float rel0 = d ? rot : rel;
            const float rel1 = d ? rel : rot;
            __half xh[8];
            #pragma unroll
            for (int kk = 0; kk < 8; kk++) {
                const int k = d * 8 + kk;
                xh[kk] = __float2half_rn(lrelu_(rel0 * sWe[k * 2] + rel1 * sWe[k * 2 + 1] + sbe[k]));
            }
            *(uint4*)(sAh + r2 * STRH + d * 8) = *(uint4*)xh;
        }
        __syncthreads();
    }
}

// ============================ confidence kernel ============================
#define CONF_EPW 2
__global__ void __launch_bounds__(256)
conf_kernel(const float* __restrict__ Wc,
            const float* __restrict__ bc,
            float* __restrict__ out)
{
    const int warp  = (blockIdx.x * blockDim.x + threadIdx.x) >> 5;
    const int lane  = threadIdx.x & 31;
    const int ebase = warp * CONF_EPW;

    for (int ei = 0; ei < CONF_EPW; ei++) {
        const int e = ebase + ei;
        float l0 = 0.f, l1 = 0.f, l2 = 0.f;
        #pragma unroll
        for (int i = 0; i < 12; i++) {
            const int k = lane + 32 * i;
            if (k < 372) {
                const int q = (k >= 248) ? 2 : (k >= 124 ? 1 : 0);
                const int r = k - q * 124;
                const float v = (r < 60)
                    ? out[e * (NMODE * SEQ * 2) + q * 60 + r]
                    : g_hfin[(q * NB + e) * HDIM + (r - 60)];
                l0 += Wc[0 * 372 + k] * v;
                l1 += Wc[1 * 372 + k] * v;
                l2 += Wc[2 * 372 + k] * v;
            }
        }
        #pragma unroll
        for (int s = 16; s > 0; s >>= 1) {
            l0 += __shfl_xor_sync(0xffffffffu, l0, s);
            l1 += __shfl_xor_sync(0xffffffffu, l1, s);
            l2 += __shfl_xor_sync(0xffffffffu, l2, s);
        }
        if (lane == 0) {
            l0 += bc[0]; l1 += bc[1]; l2 += bc[2];
            const float mx = fmaxf(l0, fmaxf(l1, l2));
            const float x0 = __expf(l0 - mx), x1 = __expf(l1 - mx), x2 = __expf(l2 - mx);
            const float inv = __fdividef(1.0f, x0 + x1 + x2);
            float* cf = out + NB * (NMODE * SEQ * 2) + e * NMODE;
            cf[0] = x0 * inv; cf[1] = x1 * inv; cf[2] = x2 * inv;
        }
    }
}

extern "C" void kernel_launch(void* const* d_in, const int* in_sizes, int n_in,
                              void* d_out, int out_size)
{
    const float* traj_rel = (const float*)d_in[1];
    const float* h0   = (const float*)d_in[2];
    const float* c0   = (const float*)d_in[3];
    const float* W_ih = (const float*)d_in[4];
    const float* W_hh = (const float*)d_in[5];
    const float* b_ih = (const float*)d_in[6];
    const float* b_hh = (const float*)d_in[7];
    const float* We   = (const float*)d_in[8];
    const float* be   = (const float*)d_in[9];
    const float* Wp   = (const float*)d_in[10];
    const float* bp   = (const float*)d_in[11];
    const float* Wc   = (const float*)d_in[12];
    const float* bc   = (const float*)d_in[13];
    float* out = (float*)d_out;

    cudaFuncSetAttribute(lstm_mma,
                         cudaFuncAttributeMaxDynamicSharedMemorySize, SMEM_BYTES);

    lstm_mma<<<NCTAS, THREADS, SMEM_BYTES>>>(traj_rel, h0, c0, W_ih, W_hh,
                                             b_ih, b_hh, We, be, Wp, bp, out);
    conf_kernel<<<NB / (CONF_EPW * 8), 256>>>(Wc, bc, out);
}

// round 9
// speedup vs baseline: 5.6150x; 1.1480x over previous
#include <cuda_runtime.h>
#include <cuda_fp16.h>
#include <cstdint>

#define NB      16384
#define HDIM    64
#define SEQ     30
#define NMODE   3
#define MROWS   128
#define THREADS 256
#define NCTAS   384          // 49152 (elem,mode) rows / 128
#define STRH    88           // A row stride in halfs (44 words: conflict-free frags)
#define KS      5            // k-steps of 16 covering cols 0..79 (x16 | h64-permuted)
#define NT      32           // n-tiles of 8 gate-interleaved columns

// ---- SMEM float-unit offsets ----
#define OFF_BF  0                           // B frags: NT*KS*32 uint2 = 10240 floats
#define OFF_AH  (OFF_BF + NT * KS * 64)     // A halfs: 128*STRH = 11264 halfs = 5632 floats
#define OFF_BI  (OFF_AH + MROWS * STRH / 2) // [256] gate-interleaved bias
#define OFF_WP  (OFF_BI + 256)              // [2][64]
#define OFF_WE  (OFF_WP + 128)              // [16][2]
#define OFF_BE  (OFF_WE + 32)               // [16]
#define OFF_BP  (OFF_BE + 16)               // [2] (+2 pad)
#define SMEM_FLOATS (OFF_BP + 4)
#define SMEM_BYTES  (SMEM_FLOATS * 4)       // ~65.3 KB -> 2 CTAs/SM

__device__ float g_hfin[NMODE * NB * HDIM];

// ============================ helpers ============================
__device__ __forceinline__ void mma16(float& d0, float& d1, float& d2, float& d3,
                                      uint32_t a0, uint32_t a1, uint32_t a2, uint32_t a3,
                                      uint32_t b0, uint32_t b1) {
    asm volatile("mma.sync.aligned.m16n8k16.row.col.f32.f16.f16.f32 "
                 "{%0,%1,%2,%3}, {%4,%5,%6,%7}, {%8,%9}, {%0,%1,%2,%3};"
                 : "+f"(d0), "+f"(d1), "+f"(d2), "+f"(d3)
                 : "r"(a0), "r"(a1), "r"(a2), "r"(a3), "r"(b0), "r"(b1));
}
__device__ __forceinline__ float tanha(float x) {
    float r; asm("tanh.approx.f32 %0, %1;" : "=f"(r) : "f"(x)); return r;
}
__device__ __forceinline__ float sigf(float x) {
    return fmaf(0.5f, tanha(0.5f * x), 0.5f);
}
__device__ __forceinline__ float lrelu_(float x) { return x > 0.0f ? x : 0.01f * x; }
__device__ __forceinline__ uint32_t packh2(float a, float b) {
    __half2 h = __floats2half2_rn(a, b);
    return *(uint32_t*)&h;
}

// gate-weight value for gate-row wr at A-col k (x 0..15 | permuted h 16..79)
// h permutation: col 16+j holds unit u = 2*(j&31) + (j>>5)
__device__ __forceinline__ float wval(const float* W_ih, const float* W_hh, int wr, int k) {
    if (k < 16) return W_ih[wr * 16 + k];
    const int j = k - 16;
    const int u = 2 * (j & 31) + (j >> 5);
    return W_hh[wr * 64 + u];
}

// ============================ main kernel ============================
__global__ void __launch_bounds__(THREADS, 2)
lstm_mma(const float* __restrict__ traj_rel, const float* __restrict__ h0,
         const float* __restrict__ c0,       const float* __restrict__ W_ih,
         const float* __restrict__ W_hh,     const float* __restrict__ b_ih,
         const float* __restrict__ b_hh,     const float* __restrict__ We,
         const float* __restrict__ be,       const float* __restrict__ Wp,
         const float* __restrict__ bp,       float* __restrict__ out)
{
    extern __shared__ float sm[];
    float*  sBF = sm + OFF_BF;
    __half* sAh = (__half*)(sm + OFF_AH);
    float*  sBI = sm + OFF_BI;
    float*  sWp = sm + OFF_WP;
    float*  sWe = sm + OFF_WE;
    float*  sbe = sm + OFF_BE;
    float*  sbp = sm + OFF_BP;

    const int tid  = threadIdx.x;
    const int w    = tid >> 5;
    const int lane = tid & 31;
    const int g    = lane >> 2;            // quad id (fragment row within m-tile)
    const int tig  = lane & 3;
    const int rA   = 16 * w + g;           // fragment rows rA / rA+8
    const int row  = rA + 8 * (tig & 1);   // the row this thread's epilogue owns
    const int usel = tig >> 1;             // unit parity this thread owns
    const int m    = blockIdx.x >> 7;
    const int e0   = (blockIdx.x & 127) * MROWS;

    // ---- prologue: B fragments (f16), fragment-major, k-permuted ----
    for (int idx = tid; idx < NT * KS * 32; idx += THREADS) {
        const int lane_ = idx & 31;
        const int rest  = idx >> 5;
        const int ks    = rest % KS, nt = rest / KS;
        const int n     = nt * 8 + (lane_ >> 2);
        const int k     = ks * 16 + 2 * (lane_ & 3);
        const int u     = n >> 2, gate = n & 3, wr = gate * 64 + u;
        float lo0 = wval(W_ih, W_hh, wr, k),     lo1 = wval(W_ih, W_hh, wr, k + 1);
        float hi0 = wval(W_ih, W_hh, wr, k + 8), hi1 = wval(W_ih, W_hh, wr, k + 9);
        ((uint2*)sBF)[idx] = make_uint2(packh2(lo0, lo1), packh2(hi0, hi1));
    }
    // ---- prologue: gate-interleaved bias; A = [x0 | h0-permuted] halfs ----
    if (tid < 256) {
        const int u = tid >> 2, gate = tid & 3, wr = gate * 64 + u;
        sBI[tid] = b_ih[wr] + b_hh[wr];
    }
    for (int idx = tid; idx < MROWS * 80; idx += THREADS) {
        const int r = idx / 80, k = idx - r * 80;
        float v;
        if (k < 16) {
            float t0 = traj_rel[(e0 + r) * 2 + 0];
            float t1 = traj_rel[(e0 + r) * 2 + 1];
            v = lrelu_(t0 * We[k * 2 + 0] + t1 * We[k * 2 + 1] + be[k]);
        } else {
            const int j = k - 16;
            v = h0[(e0 + r) * HDIM + 2 * (j & 31) + (j >> 5)];
        }
        sAh[r * STRH + k] = __float2half_rn(v);
    }
    if (tid < 128) sWp[tid] = Wp[m * 128 + tid];
    if (tid < 32)  sWe[tid] = We[tid];
    if (tid < 16)  sbe[tid] = be[tid];
    if (tid < 2)   sbp[tid] = bp[m * 2 + tid];

    // per-thread cell state: (row, unit = 2*nt + usel)
    float c[NT];
    #pragma unroll
    for (int nt = 0; nt < NT; nt++)
        c[nt] = c0[(e0 + row) * HDIM + 2 * nt + usel];

    __syncthreads();      // one-time: prologue visible to all warps

    const float bp0 = sbp[0], bp1 = sbp[1];

    // persistent fragments: af[0] = x-frag (registers across iterations)
    uint32_t af[KS][4];
    af[0][0] = *(const uint32_t*)(sAh + rA * STRH + 2 * tig);
    af[0][1] = *(const uint32_t*)(sAh + (rA + 8) * STRH + 2 * tig);
    af[0][2] = *(const uint32_t*)(sAh + rA * STRH + 2 * tig + 8);
    af[0][3] = *(const uint32_t*)(sAh + (rA + 8) * STRH + 2 * tig + 8);

    for (int t = 0; t < SEQ; t++) {
        // ---- load h fragments (ks = 1..4) from own warp's rows ----
        #pragma unroll
        for (int ks = 1; ks < KS; ks++) {
            const int k0 = ks * 16 + 2 * tig;
            af[ks][0] = *(const uint32_t*)(sAh + rA * STRH + k0);
            af[ks][1] = *(const uint32_t*)(sAh + (rA + 8) * STRH + k0);
            af[ks][2] = *(const uint32_t*)(sAh + rA * STRH + k0 + 8);
            af[ks][3] = *(const uint32_t*)(sAh + (rA + 8) * STRH + k0 + 8);
        }
        __syncwarp();   // loads complete before this iteration's h stores

        float p0 = 0.0f, p1 = 0.0f;
        uint32_t hb2[NT / 2];   // packed h halves, nt-contiguous

        // ---- n-tiles in groups of 4: 4 independent accumulator chains ----
        #pragma unroll
        for (int nt4 = 0; nt4 < NT / 4; nt4++) {
            float d[4][4];
            #pragma unroll
            for (int i = 0; i < 4; i++) {
                const float2 bv = *(const float2*)(sBI + (nt4 * 4 + i) * 8 + 2 * tig);
                d[i][0] = bv.x; d[i][1] = bv.y; d[i][2] = bv.x; d[i][3] = bv.y;
            }
            const uint2* bf = (const uint2*)sBF + (nt4 * 4 * KS) * 32 + lane;
            #pragma unroll
            for (int ks = 0; ks < KS; ks++) {
                #pragma unroll
                for (int i = 0; i < 4; i++) {
                    const uint2 bv = bf[(i * KS + ks) * 32];
                    mma16(d[i][0], d[i][1], d[i][2], d[i][3],
                          af[ks][0], af[ks][1], af[ks][2], af[ks][3],
                          bv.x, bv.y);
                }
            }
            // ---- epilogue for the four tiles ----
            float hpair[4];
            #pragma unroll
            for (int i = 0; i < 4; i++) {
                const int nt = nt4 * 4 + i;
                const float d0 = d[i][0], d1 = d[i][1], d2 = d[i][2], d3 = d[i][3];
                const bool  odd = tig & 1;
                const float s0 = odd ? d0 : d2;
                const float s1 = odd ? d1 : d3;
                const float q0 = __shfl_xor_sync(0xffffffffu, s0, 1);
                const float q1 = __shfl_xor_sync(0xffffffffu, s1, 1);
                const float gi = odd ? q0 : d0;
                const float gf = odd ? q1 : d1;
                const float gg = odd ? d2 : q0;
                const float go = odd ? d3 : q1;
                const float iv = sigf(gi);
                const float fv = sigf(gf);
                const float gv = tanha(gg);
                const float ov = sigf(go);
                const float cn = fv * c[nt] + iv * gv;
                c[nt] = cn;
                const float h = ov * tanha(cn);
                const int   u = 2 * nt + usel;
                p0 += h * sWp[u];
                p1 += h * sWp[64 + u];
                hpair[i] = h;
                if (t == SEQ - 1)
                    g_hfin[(m * NB + e0 + row) * HDIM + u] = h;
            }
            hb2[nt4 * 2 + 0] = packh2(hpair[0], hpair[1]);
            hb2[nt4 * 2 + 1] = packh2(hpair[2], hpair[3]);
        }

        // ---- h writeback: 4 x STS.128, contiguous (col 16 + 32*usel + nt) ----
        {
            __half* dst = sAh + row * STRH + 16 + 32 * usel;
            *(uint4*)(dst)      = make_uint4(hb2[0],  hb2[1],  hb2[2],  hb2[3]);
            *(uint4*)(dst + 8)  = make_uint4(hb2[4],  hb2[5],  hb2[6],  hb2[7]);
            *(uint4*)(dst + 16) = make_uint4(hb2[8],  hb2[9],  hb2[10], hb2[11]);
            *(uint4*)(dst + 24) = make_uint4(hb2[12], hb2[13], hb2[14], hb2[15]);
        }

        // ---- rel_pos + next x fragment, all in-warp ----
        // full row-sums: pair (tig, tig^2) shares a row
        p0 += __shfl_xor_sync(0xffffffffu, p0, 2);
        p1 += __shfl_xor_sync(0xffffffffu, p1, 2);
        // owner of row16 r: lane 4*(r&7) + (r>>3); rows needed: g (rA) and g+8 (rA+8)
        const float v0a = __shfl_sync(0xffffffffu, p0, 4 * g);
        const float v1a = __shfl_sync(0xffffffffu, p1, 4 * g);
        const float v0b = __shfl_sync(0xffffffffu, p0, 4 * g + 1);
        const float v1b = __shfl_sync(0xffffffffu, p1, 4 * g + 1);
        const float ra0 = v0a + bp0, ra1 = v1a + bp1;   // rel_pos(rA)
        const float rb0 = v0b + bp0, rb1 = v1b + bp1;   // rel_pos(rA+8)
        if (tig < 2) {
            float2 rv = tig ? make_float2(rb0, rb1) : make_float2(ra0, ra1);
            *(float2*)(out + (size_t)(e0 + rA + 8 * tig) * (NMODE * SEQ * 2)
                           + m * (SEQ * 2) + t * 2) = rv;
        }
        // next x fragment: cols 2tig,2tig+1 (lo) and +8 (hi) for rows rA, rA+8
        {
            const int k0 = 2 * tig;
            #pragma unroll
            for (int hh = 0; hh < 2; hh++) {            // hh=0 -> cols k0, k0+1 ; hh=1 -> +8
                const int ka = k0 + 8 * hh, kb = ka + 1;
                const float xa0 = lrelu_(fmaf(ra0, sWe[ka * 2], fmaf(ra1, sWe[ka * 2 + 1], sbe[ka])));
                const float xa1 = lrelu_(fmaf(ra0, sWe[kb * 2], fmaf(ra1, sWe[kb * 2 + 1], sbe[kb])));
                const float xb0 = lrelu_(fmaf(rb0, sWe[ka * 2], fmaf(rb1, sWe[ka * 2 + 1], sbe[ka])));
                const float xb1 = lrelu_(fmaf(rb0, sWe[kb * 2], fmaf(rb1, sWe[kb * 2 + 1], sbe[kb])));
                af[0][0 + hh * 2] = packh2(xa0, xa1);
                af[0][1 + hh * 2] = packh2(xb0, xb1);
            }
        }
        __syncwarp();   // h stores visible before next iteration's loads
    }
}

// ============================ confidence kernel ============================
#define CONF_EPW 2
__global__ void __launch_bounds__(256)
conf_kernel(const float* __restrict__ Wc,
            const float* __restrict__ bc,
            float* __restrict__ out)
{
    const int warp  = (blockIdx.x * blockDim.x + threadIdx.x) >> 5;
    const int lane  = threadIdx.x & 31;
    const int ebase = warp * CONF_EPW;

    for (int ei = 0; ei < CONF_EPW; ei++) {
        const int e = ebase + ei;
        float l0 = 0.f, l1 = 0.f, l2 = 0.f;
        #pragma unroll
        for (int i = 0; i < 12; i++) {
            const int k = lane + 32 * i;
            if (k < 372) {
                const int q = (k >= 248) ? 2 : (k >= 124 ? 1 : 0);
                const int r = k - q * 124;
                const float v = (r < 60)
                    ? out[e * (NMODE * SEQ * 2) + q * 60 + r]
                    : g_hfin[(q * NB + e) * HDIM + (r - 60)];
                l0 += Wc[0 * 372 + k] * v;
                l1 += Wc[1 * 372 + k] * v;
                l2 += Wc[2 * 372 + k] * v;
            }
        }
        #pragma unroll
        for (int s = 16; s > 0; s >>= 1) {
            l0 += __shfl_xor_sync(0xffffffffu, l0, s);
            l1 += __shfl_xor_sync(0xffffffffu, l1, s);
            l2 += __shfl_xor_sync(0xffffffffu, l2, s);
        }
        if (lane == 0) {
            l0 += bc[0]; l1 += bc[1]; l2 += bc[2];
            const float mx = fmaxf(l0, fmaxf(l1, l2));
            const float x0 = __expf(l0 - mx), x1 = __expf(l1 - mx), x2 = __expf(l2 - mx);
            const float inv = __fdividef(1.0f, x0 + x1 + x2);
            float* cf = out + NB * (NMODE * SEQ * 2) + e * NMODE;
            cf[0] = x0 * inv; cf[1] = x1 * inv; cf[2] = x2 * inv;
        }
    }
}

extern "C" void kernel_launch(void* const* d_in, const int* in_sizes, int n_in,
                              void* d_out, int out_size)
{
    const float* traj_rel = (const float*)d_in[1];
    const float* h0   = (const float*)d_in[2];
    const float* c0   = (const float*)d_in[3];
    const float* W_ih = (const float*)d_in[4];
    const float* W_hh = (const float*)d_in[5];
    const float* b_ih = (const float*)d_in[6];
    const float* b_hh = (const float*)d_in[7];
    const float* We   = (const float*)d_in[8];
    const float* be   = (const float*)d_in[9];
    const float* Wp   = (const float*)d_in[10];
    const float* bp   = (const float*)d_in[11];
    const float* Wc   = (const float*)d_in[12];
    const float* bc   = (const float*)d_in[13];
    float* out = (float*)d_out;

    cudaFuncSetAttribute(lstm_mma,
                         cudaFuncAttributeMaxDynamicSharedMemorySize, SMEM_BYTES);

    lstm_mma<<<NCTAS, THREADS, SMEM_BYTES>>>(traj_rel, h0, c0, W_ih, W_hh,
                                             b_ih, b_hh, We, be, Wp, bp, out);
    conf_kernel<<<NB / (CONF_EPW * 8), 256>>>(Wc, bc, out);
}